// round 1
// baseline (speedup 1.0000x reference)
#include <cuda_runtime.h>

#define BATCH 2
#define HEADS 16
#define SEQ   2048
#define DIM   1024
#define HDIM  64
#define MTOT  (BATCH*SEQ)   // 4096

// Scratch (device globals: allocation-free rule)
__device__ float g_q[BATCH*HEADS*SEQ*HDIM];   // [b,h,s,dh]
__device__ float g_k[BATCH*HEADS*SEQ*HDIM];
__device__ float g_v[BATCH*HEADS*SEQ*HDIM];
__device__ float g_ao[BATCH*SEQ*DIM];         // scrambled attn output, (b, s', d')

// ---------------------------------------------------------------------------
// GEMM: C = A(M=4096,K=1024) @ W^T(N=1024,K=1024) + bias
// mode 0: epilogue scatters into [b,h,s,dh] layout (QKV projections)
// mode 1: plain row-major [m][n] (final projection -> d_out)
// BM=BN=64, BK=16, 128 threads, 4x8 micro-tile per thread.
// ---------------------------------------------------------------------------
__global__ __launch_bounds__(128) void gemm_kernel(
    const float* __restrict__ A, const float* __restrict__ W,
    const float* __restrict__ bias, float* __restrict__ C, int mode)
{
    __shared__ alignas(16) float As[16][68];   // [k][m]
    __shared__ alignas(16) float Ws[16][68];   // [k][n]
    const int tid = threadIdx.x;
    const int m0 = blockIdx.y * 64;
    const int n0 = blockIdx.x * 64;
    const int r0 = (tid >> 3) * 4;   // 16 row groups
    const int c0 = (tid & 7) * 8;    // 8 col groups

    float acc[4][8];
    #pragma unroll
    for (int i = 0; i < 4; i++)
        #pragma unroll
        for (int j = 0; j < 8; j++) acc[i][j] = 0.f;

    for (int kb = 0; kb < DIM; kb += 16) {
        #pragma unroll
        for (int l = 0; l < 2; l++) {
            int i  = tid + l * 128;       // 0..255 float4 slots
            int m  = i >> 2;              // 0..63
            int kq = (i & 3) << 2;        // 0,4,8,12
            float4 av = *(const float4*)(A + (size_t)(m0 + m) * DIM + kb + kq);
            As[kq+0][m] = av.x; As[kq+1][m] = av.y;
            As[kq+2][m] = av.z; As[kq+3][m] = av.w;
            float4 wv = *(const float4*)(W + (size_t)(n0 + m) * DIM + kb + kq);
            Ws[kq+0][m] = wv.x; Ws[kq+1][m] = wv.y;
            Ws[kq+2][m] = wv.z; Ws[kq+3][m] = wv.w;
        }
        __syncthreads();
        #pragma unroll
        for (int kk = 0; kk < 16; kk++) {
            float4 a  = *(const float4*)&As[kk][r0];
            float4 b0 = *(const float4*)&Ws[kk][c0];
            float4 b1 = *(const float4*)&Ws[kk][c0 + 4];
            float av[4] = {a.x, a.y, a.z, a.w};
            float bv[8] = {b0.x, b0.y, b0.z, b0.w, b1.x, b1.y, b1.z, b1.w};
            #pragma unroll
            for (int i = 0; i < 4; i++)
                #pragma unroll
                for (int j = 0; j < 8; j++)
                    acc[i][j] = fmaf(av[i], bv[j], acc[i][j]);
        }
        __syncthreads();
    }

    #pragma unroll
    for (int i = 0; i < 4; i++) {
        int m = m0 + r0 + i;
        #pragma unroll
        for (int j = 0; j < 8; j++) {
            int n = n0 + c0 + j;
            float val = acc[i][j] + bias[n];
            if (mode == 0) {
                int b = m >> 11, s = m & 2047;
                int h = n >> 6,  dh = n & 63;
                C[(((size_t)(b * HEADS + h)) * SEQ + s) * HDIM + dh] = val;
            } else {
                C[(size_t)m * DIM + n] = val;
            }
        }
    }
}

// ---------------------------------------------------------------------------
// Flash-style attention with faithful -1e-9 mask fill (dense softmax!) and
// scrambled-transpose epilogue scatter.
// One CTA = one (b,h) and 64 query rows. 128 threads.
// ---------------------------------------------------------------------------
struct AttnSmem {
    float Qs[64][68];   // [d][r]  (transposed)
    float Ks[64][68];   // [d][c]  (transposed)
    float Vs[64][68];   // [j][d]
    float Ss[64][68];   // [r][c]  scores, then probabilities
    float m_s[64], l_s[64], a_s[64];
};

__global__ __launch_bounds__(128) void attn_kernel(
    const float* __restrict__ q, const float* __restrict__ k,
    const float* __restrict__ v, float* __restrict__ ao)
{
    extern __shared__ char smraw[];
    AttnSmem& sm = *reinterpret_cast<AttnSmem*>(smraw);

    const int tid = threadIdx.x;
    const int bh  = blockIdx.y;
    const int b   = bh >> 4;
    const int h   = bh & 15;
    const int q0  = blockIdx.x * 64;
    const float scale = 0.125f;   // HDIM^-0.5

    const float* qp = q + (size_t)bh * SEQ * HDIM;
    const float* kp = k + (size_t)bh * SEQ * HDIM;
    const float* vp = v + (size_t)bh * SEQ * HDIM;

    // load Q tile transposed: Qs[d][r]
    for (int i = tid; i < 64 * 16; i += 128) {
        int r = i >> 4, dq = (i & 15) << 2;
        float4 t = *(const float4*)&qp[(size_t)(q0 + r) * HDIM + dq];
        sm.Qs[dq+0][r] = t.x; sm.Qs[dq+1][r] = t.y;
        sm.Qs[dq+2][r] = t.z; sm.Qs[dq+3][r] = t.w;
    }
    if (tid < 64) { sm.m_s[tid] = -1e30f; sm.l_s[tid] = 0.f; }

    const int r0 = (tid >> 3) * 4;
    const int c0 = (tid & 7) * 8;
    float o[4][8];
    #pragma unroll
    for (int i = 0; i < 4; i++)
        #pragma unroll
        for (int j = 0; j < 8; j++) o[i][j] = 0.f;
    __syncthreads();

    for (int kt = 0; kt < 32; kt++) {       // ALL tiles: mask is -1e-9, not -inf
        const int k0 = kt * 64;
        for (int i = tid; i < 64 * 16; i += 128) {
            int r = i >> 4, dq = (i & 15) << 2;
            float4 tk = *(const float4*)&kp[(size_t)(k0 + r) * HDIM + dq];
            sm.Ks[dq+0][r] = tk.x; sm.Ks[dq+1][r] = tk.y;
            sm.Ks[dq+2][r] = tk.z; sm.Ks[dq+3][r] = tk.w;
            float4 tv = *(const float4*)&vp[(size_t)(k0 + r) * HDIM + dq];
            *(float4*)&sm.Vs[r][dq] = tv;
        }
        __syncthreads();

        // Phase A: scores S = Q @ K^T  (4x8 micro-tile, rows warp-local)
        float acc[4][8];
        #pragma unroll
        for (int i = 0; i < 4; i++)
            #pragma unroll
            for (int j = 0; j < 8; j++) acc[i][j] = 0.f;
        #pragma unroll 8
        for (int d = 0; d < 64; d++) {
            float4 a  = *(const float4*)&sm.Qs[d][r0];
            float4 b0 = *(const float4*)&sm.Ks[d][c0];
            float4 b1 = *(const float4*)&sm.Ks[d][c0 + 4];
            float av[4] = {a.x, a.y, a.z, a.w};
            float bv[8] = {b0.x, b0.y, b0.z, b0.w, b1.x, b1.y, b1.z, b1.w};
            #pragma unroll
            for (int i = 0; i < 4; i++)
                #pragma unroll
                for (int j = 0; j < 8; j++)
                    acc[i][j] = fmaf(av[i], bv[j], acc[i][j]);
        }
        #pragma unroll
        for (int i = 0; i < 4; i++) {
            int qi = q0 + r0 + i;
            #pragma unroll
            for (int j = 0; j < 8; j++) {
                int kj = k0 + c0 + j;
                sm.Ss[r0 + i][c0 + j] = (kj > qi) ? -1e-9f : acc[i][j] * scale;
            }
        }
        __syncwarp();   // rows of Ss / softmax state are warp-local

        // Phase B: online softmax update (2 threads per row, 32 cols each)
        {
            int r  = tid >> 1;
            int cb = (tid & 1) * 32;
            float mloc = -1e30f;
            #pragma unroll 8
            for (int j = 0; j < 32; j++) mloc = fmaxf(mloc, sm.Ss[r][cb + j]);
            mloc = fmaxf(mloc, __shfl_xor_sync(0xffffffffu, mloc, 1));
            float mold = sm.m_s[r];
            float mnew = fmaxf(mold, mloc);
            float sum = 0.f;
            #pragma unroll 8
            for (int j = 0; j < 32; j++) {
                float p = __expf(sm.Ss[r][cb + j] - mnew);
                sm.Ss[r][cb + j] = p;
                sum += p;
            }
            sum += __shfl_xor_sync(0xffffffffu, sum, 1);
            if ((tid & 1) == 0) {
                float alpha = __expf(mold - mnew);
                sm.a_s[r] = alpha;
                sm.l_s[r] = sm.l_s[r] * alpha + sum;
                sm.m_s[r] = mnew;
            }
        }
        __syncwarp();

        // Phase C: O = O*alpha + P @ V (4x8 micro-tile)
        float al[4];
        #pragma unroll
        for (int i = 0; i < 4; i++) al[i] = sm.a_s[r0 + i];
        #pragma unroll
        for (int i = 0; i < 4; i++)
            #pragma unroll
            for (int j = 0; j < 8; j++) o[i][j] *= al[i];
        #pragma unroll 4
        for (int jj = 0; jj < 64; jj++) {
            float p[4];
            #pragma unroll
            for (int i = 0; i < 4; i++) p[i] = sm.Ss[r0 + i][jj];
            float4 v0 = *(const float4*)&sm.Vs[jj][c0];
            float4 v1 = *(const float4*)&sm.Vs[jj][c0 + 4];
            float vv[8] = {v0.x, v0.y, v0.z, v0.w, v1.x, v1.y, v1.z, v1.w};
            #pragma unroll
            for (int i = 0; i < 4; i++)
                #pragma unroll
                for (int j = 0; j < 8; j++)
                    o[i][j] = fmaf(p[i], vv[j], o[i][j]);
        }
        __syncthreads();   // protect Ks/Vs/Ss reuse next tile
    }

    // Epilogue: normalize and scatter into the buggy transpose+reshape layout:
    // element [b,h,s,dh] -> ao[b][2*c + (s>>10)][s & 1023], c = h*64+dh
    float linv[4];
    #pragma unroll
    for (int i = 0; i < 4; i++) linv[i] = 1.0f / sm.l_s[r0 + i];
    #pragma unroll
    for (int i = 0; i < 4; i++) {
        int s = q0 + r0 + i;
        #pragma unroll
        for (int j = 0; j < 8; j++) {
            int c = h * 64 + c0 + j;
            size_t idx = (size_t)b * SEQ * DIM
                       + (size_t)(2 * c + (s >> 10)) * DIM + (s & 1023);
            ao[idx] = o[i][j] * linv[i];
        }
    }
}

// ---------------------------------------------------------------------------
extern "C" void kernel_launch(void* const* d_in, const int* in_sizes, int n_in,
                              void* d_out, int out_size)
{
    const float* x  = (const float*)d_in[0];
    // d_in[1] = masks (tril) — reproduced analytically, not read
    const float* Wq = (const float*)d_in[2];
    const float* bq = (const float*)d_in[3];
    const float* Wk = (const float*)d_in[4];
    const float* bk = (const float*)d_in[5];
    const float* Wv = (const float*)d_in[6];
    const float* bv = (const float*)d_in[7];
    const float* Wo = (const float*)d_in[8];
    const float* bo = (const float*)d_in[9];
    float* out = (float*)d_out;

    float *q, *k, *v, *ao;
    cudaGetSymbolAddress((void**)&q,  g_q);
    cudaGetSymbolAddress((void**)&k,  g_k);
    cudaGetSymbolAddress((void**)&v,  g_v);
    cudaGetSymbolAddress((void**)&ao, g_ao);

    cudaFuncSetAttribute(attn_kernel,
                         cudaFuncAttributeMaxDynamicSharedMemorySize,
                         (int)sizeof(AttnSmem));

    dim3 gg(DIM / 64, MTOT / 64);   // (16, 64)
    gemm_kernel<<<gg, 128>>>(x, Wq, bq, q, 0);
    gemm_kernel<<<gg, 128>>>(x, Wk, bk, k, 0);
    gemm_kernel<<<gg, 128>>>(x, Wv, bv, v, 0);

    dim3 ga(SEQ / 64, BATCH * HEADS);  // (32, 32)
    attn_kernel<<<ga, 128, sizeof(AttnSmem)>>>(q, k, v, ao);

    gemm_kernel<<<gg, 128>>>(ao, Wo, bo, out, 1);
}

// round 2
// speedup vs baseline: 4.4731x; 4.4731x over previous
#include <cuda_runtime.h>

#define BATCH 2
#define HEADS 16
#define SEQ   2048
#define DIM   1024
#define HDIM  64
#define MTOT  (BATCH*SEQ)   // 4096
#define SCALE 0.125f

// Scratch (device globals: allocation-free rule)
__device__ float g_q[BATCH*HEADS*SEQ*HDIM];   // [b,h,s,dh]
__device__ float g_k[BATCH*HEADS*SEQ*HDIM];
__device__ float g_v[BATCH*HEADS*SEQ*HDIM];
__device__ float g_ao[BATCH*SEQ*DIM];         // scrambled attn output

// ---------------------------------------------------------------------------
// tf32 helpers
// ---------------------------------------------------------------------------
__device__ __forceinline__ unsigned f2tf(float x) {
    unsigned r;
    asm("cvt.rna.tf32.f32 %0, %1;" : "=r"(r) : "f"(x));
    return r;
}
__device__ __forceinline__ float4 cvt4(float4 v) {
    v.x = __uint_as_float(f2tf(v.x));
    v.y = __uint_as_float(f2tf(v.y));
    v.z = __uint_as_float(f2tf(v.z));
    v.w = __uint_as_float(f2tf(v.w));
    return v;
}
__device__ __forceinline__ void mma_tf32(float c[4], const unsigned a[4], const unsigned b[2]) {
    asm volatile(
        "mma.sync.aligned.m16n8k8.row.col.f32.tf32.tf32.f32 "
        "{%0,%1,%2,%3}, {%4,%5,%6,%7}, {%8,%9}, {%0,%1,%2,%3};\n"
        : "+f"(c[0]), "+f"(c[1]), "+f"(c[2]), "+f"(c[3])
        : "r"(a[0]), "r"(a[1]), "r"(a[2]), "r"(a[3]), "r"(b[0]), "r"(b[1]));
}

// ---------------------------------------------------------------------------
// GEMM: C = A(4096x1024) @ W^T(1024x1024) + bias, tf32 tensor cores
// BM=128, BN=128, BK=32, 256 threads, warp grid 2x4 (warp tile 64x32)
// mode 0: scatter into [b,h,s,dh]; mode 1: plain row-major
// ---------------------------------------------------------------------------
__global__ __launch_bounds__(256) void gemm_tc(
    const float* __restrict__ A, const float* __restrict__ W,
    const float* __restrict__ bias, float* __restrict__ C, int mode)
{
    __shared__ float As[128][36];
    __shared__ float Ws[128][36];
    const int tid  = threadIdx.x;
    const int lane = tid & 31, wid = tid >> 5;
    const int g = lane >> 2, tg = lane & 3;
    const int m0 = blockIdx.y * 128, n0 = blockIdx.x * 128;
    const int wm0 = (wid >> 2) * 64, wn0 = (wid & 3) * 32;

    float acc[4][4][4];
    #pragma unroll
    for (int mt = 0; mt < 4; mt++)
        #pragma unroll
        for (int nt = 0; nt < 4; nt++)
            #pragma unroll
            for (int r = 0; r < 4; r++) acc[mt][nt][r] = 0.f;

    const int r_ld = tid >> 3;          // 0..31
    const int c_ld = (tid & 7) * 4;     // 0,4,..,28

    for (int kb = 0; kb < DIM; kb += 32) {
        #pragma unroll
        for (int i = 0; i < 4; i++) {
            int r = r_ld + i * 32;
            float4 av = *(const float4*)(A + (size_t)(m0 + r) * DIM + kb + c_ld);
            float4 wv = *(const float4*)(W + (size_t)(n0 + r) * DIM + kb + c_ld);
            *(float4*)&As[r][c_ld] = cvt4(av);
            *(float4*)&Ws[r][c_ld] = cvt4(wv);
        }
        __syncthreads();
        #pragma unroll
        for (int ks = 0; ks < 4; ks++) {
            const int k0 = ks * 8;
            unsigned af[4][4], bf[4][2];
            #pragma unroll
            for (int mt = 0; mt < 4; mt++) {
                const float* p = &As[wm0 + mt*16 + g][k0 + tg];
                af[mt][0] = __float_as_uint(p[0]);
                af[mt][1] = __float_as_uint(p[8*36]);
                af[mt][2] = __float_as_uint(p[4]);
                af[mt][3] = __float_as_uint(p[8*36 + 4]);
            }
            #pragma unroll
            for (int nt = 0; nt < 4; nt++) {
                const float* p = &Ws[wn0 + nt*8 + g][k0 + tg];
                bf[nt][0] = __float_as_uint(p[0]);
                bf[nt][1] = __float_as_uint(p[4]);
            }
            #pragma unroll
            for (int mt = 0; mt < 4; mt++)
                #pragma unroll
                for (int nt = 0; nt < 4; nt++)
                    mma_tf32(acc[mt][nt], af[mt], bf[nt]);
        }
        __syncthreads();
    }

    #pragma unroll
    for (int mt = 0; mt < 4; mt++) {
        #pragma unroll
        for (int nt = 0; nt < 4; nt++) {
            int col = n0 + wn0 + nt*8 + tg*2;
            float b0v = bias[col], b1v = bias[col + 1];
            #pragma unroll
            for (int h2 = 0; h2 < 2; h2++) {
                int row = m0 + wm0 + mt*16 + g + h2*8;
                float v0 = acc[mt][nt][h2*2 + 0] + b0v;
                float v1 = acc[mt][nt][h2*2 + 1] + b1v;
                size_t idx;
                if (mode == 0) {
                    int b = row >> 11, s = row & 2047;
                    int hh = col >> 6, dh = col & 63;
                    idx = (((size_t)(b * HEADS + hh)) * SEQ + s) * HDIM + dh;
                } else {
                    idx = (size_t)row * DIM + col;
                }
                *(float2*)(C + idx) = make_float2(v0, v1);
            }
        }
    }
}

// ---------------------------------------------------------------------------
// Attention, tf32 tensor cores. Dense softmax (mask = -1e-9 => exp == 1.0f),
// no max subtraction, no online rescaling.
// CTA: 64 queries x one (b,h), 128 threads, warps 2x2 (32 rows x 32 cols each)
// ---------------------------------------------------------------------------
#define ASTR 68
#define VSTR 72

struct ASmem {
    float Qs[64][ASTR];
    float Ks[64][ASTR];
    float Ps[64][ASTR];
    float Vs[64][VSTR];
    float lsum[64][2];
};

__global__ __launch_bounds__(128) void attn_tc(
    const float* __restrict__ q, const float* __restrict__ k,
    const float* __restrict__ v, float* __restrict__ ao)
{
    extern __shared__ char smraw[];
    ASmem& sm = *reinterpret_cast<ASmem*>(smraw);

    const int tid  = threadIdx.x;
    const int lane = tid & 31, wid = tid >> 5;
    const int g = lane >> 2, tg = lane & 3;
    const int wm = wid >> 1, wn = wid & 1;
    const int bh = blockIdx.y, b = bh >> 4, h = bh & 15;
    const int q0 = blockIdx.x * 64;

    const float* qp = q + (size_t)bh * SEQ * HDIM;
    const float* kp = k + (size_t)bh * SEQ * HDIM;
    const float* vp = v + (size_t)bh * SEQ * HDIM;

    // load Q (tf32-rounded), row-major [s][dh]
    #pragma unroll
    for (int i = 0; i < 8; i++) {
        int idx = tid + i * 128;
        int r = idx >> 4, c4 = (idx & 15) * 4;
        *(float4*)&sm.Qs[r][c4] = cvt4(*(const float4*)(qp + (size_t)(q0 + r) * HDIM + c4));
    }

    float o[2][4][4];
    float rs[2][2] = {{0.f, 0.f}, {0.f, 0.f}};
    #pragma unroll
    for (int mt = 0; mt < 2; mt++)
        #pragma unroll
        for (int nt = 0; nt < 4; nt++)
            #pragma unroll
            for (int r = 0; r < 4; r++) o[mt][nt][r] = 0.f;

    for (int kt = 0; kt < 32; kt++) {
        const int k0t = kt * 64;
        #pragma unroll
        for (int i = 0; i < 8; i++) {
            int idx = tid + i * 128;
            int r = idx >> 4, c4 = (idx & 15) * 4;
            *(float4*)&sm.Ks[r][c4] = cvt4(*(const float4*)(kp + (size_t)(k0t + r) * HDIM + c4));
            *(float4*)&sm.Vs[r][c4] = cvt4(*(const float4*)(vp + (size_t)(k0t + r) * HDIM + c4));
        }
        __syncthreads();

        // S = Q @ K^T
        float s[2][4][4];
        #pragma unroll
        for (int mt = 0; mt < 2; mt++)
            #pragma unroll
            for (int nt = 0; nt < 4; nt++)
                #pragma unroll
                for (int r = 0; r < 4; r++) s[mt][nt][r] = 0.f;
        #pragma unroll
        for (int ks = 0; ks < 8; ks++) {
            const int k0 = ks * 8;
            unsigned aq[2][4], bk[4][2];
            #pragma unroll
            for (int mt = 0; mt < 2; mt++) {
                const float* p = &sm.Qs[wm*32 + mt*16 + g][k0 + tg];
                aq[mt][0] = __float_as_uint(p[0]);
                aq[mt][1] = __float_as_uint(p[8*ASTR]);
                aq[mt][2] = __float_as_uint(p[4]);
                aq[mt][3] = __float_as_uint(p[8*ASTR + 4]);
            }
            #pragma unroll
            for (int nt = 0; nt < 4; nt++) {
                const float* p = &sm.Ks[wn*32 + nt*8 + g][k0 + tg];
                bk[nt][0] = __float_as_uint(p[0]);
                bk[nt][1] = __float_as_uint(p[4]);
            }
            #pragma unroll
            for (int mt = 0; mt < 2; mt++)
                #pragma unroll
                for (int nt = 0; nt < 4; nt++)
                    mma_tf32(s[mt][nt], aq[mt], bk[nt]);
        }

        // mask + exp + store P (tf32) + row-sum partials
        #pragma unroll
        for (int mt = 0; mt < 2; mt++) {
            int rowg = q0 + wm*32 + mt*16 + g;
            #pragma unroll
            for (int nt = 0; nt < 4; nt++) {
                int colj = k0t + wn*32 + nt*8 + tg*2;
                float p0 = (colj     > rowg    ) ? 1.f : __expf(s[mt][nt][0] * SCALE);
                float p1 = (colj + 1 > rowg    ) ? 1.f : __expf(s[mt][nt][1] * SCALE);
                float p2 = (colj     > rowg + 8) ? 1.f : __expf(s[mt][nt][2] * SCALE);
                float p3 = (colj + 1 > rowg + 8) ? 1.f : __expf(s[mt][nt][3] * SCALE);
                rs[mt][0] += p0 + p1;
                rs[mt][1] += p2 + p3;
                int lr = wm*32 + mt*16 + g, lc = wn*32 + nt*8 + tg*2;
                *(float2*)&sm.Ps[lr][lc] =
                    make_float2(__uint_as_float(f2tf(p0)), __uint_as_float(f2tf(p1)));
                *(float2*)&sm.Ps[lr + 8][lc] =
                    make_float2(__uint_as_float(f2tf(p2)), __uint_as_float(f2tf(p3)));
            }
        }
        __syncthreads();

        // O += P @ V
        #pragma unroll
        for (int ks = 0; ks < 8; ks++) {
            const int k0 = ks * 8;
            unsigned ap[2][4], bv[4][2];
            #pragma unroll
            for (int mt = 0; mt < 2; mt++) {
                const float* p = &sm.Ps[wm*32 + mt*16 + g][k0 + tg];
                ap[mt][0] = __float_as_uint(p[0]);
                ap[mt][1] = __float_as_uint(p[8*ASTR]);
                ap[mt][2] = __float_as_uint(p[4]);
                ap[mt][3] = __float_as_uint(p[8*ASTR + 4]);
            }
            #pragma unroll
            for (int nt = 0; nt < 4; nt++) {
                int dhc = wn*32 + nt*8 + g;
                bv[nt][0] = __float_as_uint(sm.Vs[k0 + tg][dhc]);
                bv[nt][1] = __float_as_uint(sm.Vs[k0 + tg + 4][dhc]);
            }
            #pragma unroll
            for (int mt = 0; mt < 2; mt++)
                #pragma unroll
                for (int nt = 0; nt < 4; nt++)
                    mma_tf32(o[mt][nt], ap[mt], bv[nt]);
        }
        __syncthreads();
    }

    // reduce row sums: quad shuffle then cross-(wn) via smem
    #pragma unroll
    for (int mt = 0; mt < 2; mt++)
        #pragma unroll
        for (int hh = 0; hh < 2; hh++) {
            float vv = rs[mt][hh];
            vv += __shfl_xor_sync(0xffffffffu, vv, 1);
            vv += __shfl_xor_sync(0xffffffffu, vv, 2);
            rs[mt][hh] = vv;
        }
    if (tg == 0) {
        #pragma unroll
        for (int mt = 0; mt < 2; mt++) {
            sm.lsum[wm*32 + mt*16 + g][wn]     = rs[mt][0];
            sm.lsum[wm*32 + mt*16 + g + 8][wn] = rs[mt][1];
        }
    }
    __syncthreads();

    // normalize + scatter into scrambled layout:
    // [b,h,s,dh] -> ao[b][2c + (s>>10)][s & 1023], c = h*64+dh
    #pragma unroll
    for (int mt = 0; mt < 2; mt++) {
        float inv[2];
        #pragma unroll
        for (int h2 = 0; h2 < 2; h2++) {
            int lr = wm*32 + mt*16 + g + h2*8;
            inv[h2] = 1.0f / (sm.lsum[lr][0] + sm.lsum[lr][1]);
        }
        #pragma unroll
        for (int nt = 0; nt < 4; nt++) {
            #pragma unroll
            for (int h2 = 0; h2 < 2; h2++) {
                int sgl = q0 + wm*32 + mt*16 + g + h2*8;
                #pragma unroll
                for (int c2 = 0; c2 < 2; c2++) {
                    int dh = wn*32 + nt*8 + tg*2 + c2;
                    int c  = h * 64 + dh;
                    size_t idx = (size_t)b * SEQ * DIM
                               + (size_t)(2*c + (sgl >> 10)) * DIM + (sgl & 1023);
                    ao[idx] = o[mt][nt][h2*2 + c2] * inv[h2];
                }
            }
        }
    }
}

// ---------------------------------------------------------------------------
extern "C" void kernel_launch(void* const* d_in, const int* in_sizes, int n_in,
                              void* d_out, int out_size)
{
    const float* x  = (const float*)d_in[0];
    const float* Wq = (const float*)d_in[2];
    const float* bq = (const float*)d_in[3];
    const float* Wk = (const float*)d_in[4];
    const float* bk = (const float*)d_in[5];
    const float* Wv = (const float*)d_in[6];
    const float* bv = (const float*)d_in[7];
    const float* Wo = (const float*)d_in[8];
    const float* bo = (const float*)d_in[9];
    float* out = (float*)d_out;

    float *q, *k, *v, *ao;
    cudaGetSymbolAddress((void**)&q,  g_q);
    cudaGetSymbolAddress((void**)&k,  g_k);
    cudaGetSymbolAddress((void**)&v,  g_v);
    cudaGetSymbolAddress((void**)&ao, g_ao);

    cudaFuncSetAttribute(attn_tc,
                         cudaFuncAttributeMaxDynamicSharedMemorySize,
                         (int)sizeof(ASmem));

    dim3 gg(DIM / 128, MTOT / 128);   // (8, 32)
    gemm_tc<<<gg, 256>>>(x, Wq, bq, q, 0);
    gemm_tc<<<gg, 256>>>(x, Wk, bk, k, 0);
    gemm_tc<<<gg, 256>>>(x, Wv, bv, v, 0);

    dim3 ga(SEQ / 64, BATCH * HEADS);  // (32, 32)
    attn_tc<<<ga, 128, sizeof(ASmem)>>>(q, k, v, ao);

    gemm_tc<<<gg, 256>>>(ao, Wo, bo, out, 1);
}

// round 4
// speedup vs baseline: 7.8356x; 1.7517x over previous
#include <cuda_runtime.h>
#include <cuda_fp16.h>
#include <cstdint>

#define BATCH 2
#define HEADS 16
#define SEQ   2048
#define DIM   1024
#define HDIM  64
#define MTOT  (BATCH*SEQ)   // 4096
#define SCALE 0.125f

// Scratch (device globals: allocation-free rule)
__device__ __half g_q[BATCH*HEADS*SEQ*HDIM];   // [b,h,s,dh] fp16
__device__ __half g_k[BATCH*HEADS*SEQ*HDIM];
__device__ __half g_v[BATCH*HEADS*SEQ*HDIM];
__device__ float  g_ao[BATCH*SEQ*DIM];         // scrambled attn output (f32)

// ---------------------------------------------------------------------------
// helpers
// ---------------------------------------------------------------------------
__device__ __forceinline__ uint32_t smem_u32(const void* p) {
    uint32_t a;
    asm("{ .reg .u64 t; cvta.to.shared.u64 t, %1; cvt.u32.u64 %0, t; }"
        : "=r"(a) : "l"(p));
    return a;
}
#define LDSM_X4(r0,r1,r2,r3,addr) \
    asm volatile("ldmatrix.sync.aligned.m8n8.x4.shared.b16 {%0,%1,%2,%3}, [%4];" \
        : "=r"(r0),"=r"(r1),"=r"(r2),"=r"(r3) : "r"(addr))
#define LDSM_X4_T(r0,r1,r2,r3,addr) \
    asm volatile("ldmatrix.sync.aligned.m8n8.x4.trans.shared.b16 {%0,%1,%2,%3}, [%4];" \
        : "=r"(r0),"=r"(r1),"=r"(r2),"=r"(r3) : "r"(addr))

__device__ __forceinline__ void mma_h(float c[4], const uint32_t a[4], const uint32_t b[2]) {
    asm volatile(
        "mma.sync.aligned.m16n8k16.row.col.f32.f16.f16.f32 "
        "{%0,%1,%2,%3}, {%4,%5,%6,%7}, {%8,%9}, {%0,%1,%2,%3};"
        : "+f"(c[0]), "+f"(c[1]), "+f"(c[2]), "+f"(c[3])
        : "r"(a[0]), "r"(a[1]), "r"(a[2]), "r"(a[3]), "r"(b[0]), "r"(b[1]));
}

// ---------------------------------------------------------------------------
// fp16 GEMM: C = A(4096x1024,f32) @ W^T(1024x1024,f32) + bias
// Tile 128x128, BK=32, 256 threads, warps 2x4 (64x32 each), double-buffered.
// blockIdx.z selects among 3 (W,bias,dst) sets (fused QKV).
// mode 0: scatter fp16 into [b,h,s,dh]; mode 1: f32 row-major.
// ---------------------------------------------------------------------------
#define GSTR 40                         // halves per smem row (32 data + 8 pad)
#define G_STAGE (128*GSTR)              // halves per stage

__global__ __launch_bounds__(256, 2) void gemm_h(
    const float* __restrict__ A,
    const float* __restrict__ W0, const float* __restrict__ W1, const float* __restrict__ W2,
    const float* __restrict__ B0, const float* __restrict__ B1, const float* __restrict__ B2,
    __half* __restrict__ H0, __half* __restrict__ H1, __half* __restrict__ H2,
    float* __restrict__ Cf, int mode)
{
    __shared__ __half Ah[2*G_STAGE];
    __shared__ __half Wh[2*G_STAGE];

    const int z = blockIdx.z;
    const float* W  = (z == 0) ? W0 : ((z == 1) ? W1 : W2);
    const float* Bi = (z == 0) ? B0 : ((z == 1) ? B1 : B2);
    __half* Ho      = (z == 0) ? H0 : ((z == 1) ? H1 : H2);

    const int tid = threadIdx.x, lane = tid & 31, wid = tid >> 5;
    const int g = lane >> 2, tg = lane & 3;
    const int m0 = blockIdx.y * 128, n0 = blockIdx.x * 128;
    const int wm0 = (wid >> 2) * 64, wn0 = (wid & 3) * 32;

    float acc[4][4][4];
    #pragma unroll
    for (int mt = 0; mt < 4; mt++)
        #pragma unroll
        for (int nt = 0; nt < 4; nt++)
            #pragma unroll
            for (int r = 0; r < 4; r++) acc[mt][nt][r] = 0.f;

    const int r_ld = tid >> 3, c4 = (tid & 7) * 4;

    auto ldg_sts = [&](int stage, int kb) {
        const int kbase = kb * 32;
        #pragma unroll
        for (int i = 0; i < 4; i++) {
            int r = r_ld + i * 32;
            float4 av = *(const float4*)(A + (size_t)(m0 + r) * DIM + kbase + c4);
            float4 wv = *(const float4*)(W + (size_t)(n0 + r) * DIM + kbase + c4);
            int off = stage * G_STAGE + r * GSTR + c4;
            *(__half2*)&Ah[off]     = __floats2half2_rn(av.x, av.y);
            *(__half2*)&Ah[off + 2] = __floats2half2_rn(av.z, av.w);
            *(__half2*)&Wh[off]     = __floats2half2_rn(wv.x, wv.y);
            *(__half2*)&Wh[off + 2] = __floats2half2_rn(wv.z, wv.w);
        }
    };

    // ldmatrix lane address components (bytes)
    const uint32_t aBase = smem_u32(Ah), wBase = smem_u32(Wh);
    const uint32_t aLane = (uint32_t)(((wm0 + (lane & 15)) * GSTR + (lane >> 4) * 8) * 2);
    const int bRow = (lane & 7) + ((lane & 16) ? 8 : 0);
    const int bColH = (lane & 8) ? 8 : 0;
    const uint32_t bLane = (uint32_t)(((wn0 + bRow) * GSTR + bColH) * 2);
    const uint32_t stageB = G_STAGE * 2;

    ldg_sts(0, 0);
    __syncthreads();

    for (int kb = 0; kb < 32; kb++) {
        const int cur = kb & 1;
        if (kb + 1 < 32) ldg_sts(cur ^ 1, kb + 1);

        const uint32_t aS = aBase + cur * stageB + aLane;
        const uint32_t bS = wBase + cur * stageB + bLane;
        #pragma unroll
        for (int ks = 0; ks < 2; ks++) {
            uint32_t af[4][4], bf[4][2];
            #pragma unroll
            for (int mt = 0; mt < 4; mt++)
                LDSM_X4(af[mt][0], af[mt][1], af[mt][2], af[mt][3],
                        aS + (uint32_t)((mt * 16 * GSTR + ks * 16) * 2));
            #pragma unroll
            for (int np = 0; np < 2; np++)
                LDSM_X4(bf[np*2][0], bf[np*2][1], bf[np*2+1][0], bf[np*2+1][1],
                        bS + (uint32_t)((np * 16 * GSTR + ks * 16) * 2));
            #pragma unroll
            for (int mt = 0; mt < 4; mt++)
                #pragma unroll
                for (int nt = 0; nt < 4; nt++)
                    mma_h(acc[mt][nt], af[mt], bf[nt]);
        }
        __syncthreads();
    }

    // epilogue
    #pragma unroll
    for (int mt = 0; mt < 4; mt++) {
        #pragma unroll
        for (int nt = 0; nt < 4; nt++) {
            int col = n0 + wn0 + nt * 8 + tg * 2;
            float b0v = Bi[col], b1v = Bi[col + 1];
            #pragma unroll
            for (int h2 = 0; h2 < 2; h2++) {
                int row = m0 + wm0 + mt * 16 + g + h2 * 8;
                float v0 = acc[mt][nt][h2*2 + 0] + b0v;
                float v1 = acc[mt][nt][h2*2 + 1] + b1v;
                if (mode == 0) {
                    int b = row >> 11, s = row & 2047;
                    int hh = col >> 6, dh = col & 63;
                    size_t idx = (((size_t)(b * HEADS + hh)) * SEQ + s) * HDIM + dh;
                    *(__half2*)(Ho + idx) = __floats2half2_rn(v0, v1);
                } else {
                    *(float2*)(Cf + (size_t)row * DIM + col) = make_float2(v0, v1);
                }
            }
        }
    }
}

// ---------------------------------------------------------------------------
// fp16 attention. Dense softmax (mask=-1e-9 => exp==1.0f), no max, no rescale.
// CTA: 64 queries x one (b,h), 128 threads, warps 2x2 (32 rows x 32 cols).
// All fragments via ldmatrix; V via ldmatrix.trans.
// ---------------------------------------------------------------------------
#define QSTR 72
struct AS2 {
    __half Qs[64][QSTR];
    __half Ks[64][QSTR];
    __half Ps[64][QSTR];
    __half Vs[64][QSTR];
    float  lsum[64][2];
};

__global__ __launch_bounds__(128, 4) void attn_h(
    const __half* __restrict__ q, const __half* __restrict__ k,
    const __half* __restrict__ v, float* __restrict__ ao)
{
    __shared__ AS2 sm;

    const int tid = threadIdx.x, lane = tid & 31, wid = tid >> 5;
    const int g = lane >> 2, tg = lane & 3;
    const int wm = wid >> 1, wn = wid & 1;
    const int bh = blockIdx.y, b = bh >> 4, h = bh & 15;
    const int q0 = blockIdx.x * 64;

    const __half* qp = q + (size_t)bh * SEQ * HDIM;
    const __half* kp = k + (size_t)bh * SEQ * HDIM;
    const __half* vp = v + (size_t)bh * SEQ * HDIM;

    // load Q tile (64x64 halves)
    #pragma unroll
    for (int i = 0; i < 4; i++) {
        int idx = tid + i * 128;
        int r = idx >> 3, c8 = (idx & 7) * 8;
        *(uint4*)&sm.Qs[r][c8] = *(const uint4*)(qp + (size_t)(q0 + r) * HDIM + c8);
    }

    float o[2][4][4];
    float rs[2][2] = {{0.f, 0.f}, {0.f, 0.f}};
    #pragma unroll
    for (int mt = 0; mt < 2; mt++)
        #pragma unroll
        for (int nt = 0; nt < 4; nt++)
            #pragma unroll
            for (int r = 0; r < 4; r++) o[mt][nt][r] = 0.f;

    // ldmatrix lane address components (bytes)
    const uint32_t qA = smem_u32(sm.Qs) +
        (uint32_t)(((wm*32 + (lane & 15)) * QSTR + (lane >> 4) * 8) * 2);
    const uint32_t pA = smem_u32(sm.Ps) +
        (uint32_t)(((wm*32 + (lane & 15)) * QSTR + (lane >> 4) * 8) * 2);
    const int bRow = (lane & 7) + ((lane & 16) ? 8 : 0);
    const int bColH = (lane & 8) ? 8 : 0;
    const uint32_t kB = smem_u32(sm.Ks) +
        (uint32_t)(((wn*32 + bRow) * QSTR + bColH) * 2);
    const int vRow = (lane & 7) + ((lane & 8) ? 8 : 0);
    const int vColH = (lane & 16) ? 8 : 0;
    const uint32_t vB = smem_u32(sm.Vs) +
        (uint32_t)((vRow * QSTR + wn*32 + vColH) * 2);

    for (int kt = 0; kt < 32; kt++) {
        const int k0t = kt * 64;
        #pragma unroll
        for (int i = 0; i < 4; i++) {
            int idx = tid + i * 128;
            int r = idx >> 3, c8 = (idx & 7) * 8;
            *(uint4*)&sm.Ks[r][c8] = *(const uint4*)(kp + (size_t)(k0t + r) * HDIM + c8);
            *(uint4*)&sm.Vs[r][c8] = *(const uint4*)(vp + (size_t)(k0t + r) * HDIM + c8);
        }
        __syncthreads();

        // S = Q @ K^T
        float s[2][4][4];
        #pragma unroll
        for (int mt = 0; mt < 2; mt++)
            #pragma unroll
            for (int nt = 0; nt < 4; nt++)
                #pragma unroll
                for (int r = 0; r < 4; r++) s[mt][nt][r] = 0.f;
        #pragma unroll
        for (int ks = 0; ks < 4; ks++) {
            uint32_t af[2][4], bf[4][2];
            #pragma unroll
            for (int mt = 0; mt < 2; mt++)
                LDSM_X4(af[mt][0], af[mt][1], af[mt][2], af[mt][3],
                        qA + (uint32_t)((mt * 16 * QSTR + ks * 16) * 2));
            #pragma unroll
            for (int np = 0; np < 2; np++)
                LDSM_X4(bf[np*2][0], bf[np*2][1], bf[np*2+1][0], bf[np*2+1][1],
                        kB + (uint32_t)((np * 16 * QSTR + ks * 16) * 2));
            #pragma unroll
            for (int mt = 0; mt < 2; mt++)
                #pragma unroll
                for (int nt = 0; nt < 4; nt++)
                    mma_h(s[mt][nt], af[mt], bf[nt]);
        }

        // mask + exp + row-sum partials + store P (fp16)
        #pragma unroll
        for (int mt = 0; mt < 2; mt++) {
            int rowg = q0 + wm*32 + mt*16 + g;
            #pragma unroll
            for (int nt = 0; nt < 4; nt++) {
                int colj = k0t + wn*32 + nt*8 + tg*2;
                float p0 = (colj     > rowg    ) ? 1.f : __expf(s[mt][nt][0] * SCALE);
                float p1 = (colj + 1 > rowg    ) ? 1.f : __expf(s[mt][nt][1] * SCALE);
                float p2 = (colj     > rowg + 8) ? 1.f : __expf(s[mt][nt][2] * SCALE);
                float p3 = (colj + 1 > rowg + 8) ? 1.f : __expf(s[mt][nt][3] * SCALE);
                rs[mt][0] += p0 + p1;
                rs[mt][1] += p2 + p3;
                int lr = wm*32 + mt*16 + g, lc = wn*32 + nt*8 + tg*2;
                *(__half2*)&sm.Ps[lr][lc]     = __floats2half2_rn(p0, p1);
                *(__half2*)&sm.Ps[lr + 8][lc] = __floats2half2_rn(p2, p3);
            }
        }
        __syncthreads();

        // O += P @ V
        #pragma unroll
        for (int ks = 0; ks < 4; ks++) {
            uint32_t af[2][4], bf[4][2];
            #pragma unroll
            for (int mt = 0; mt < 2; mt++)
                LDSM_X4(af[mt][0], af[mt][1], af[mt][2], af[mt][3],
                        pA + (uint32_t)((mt * 16 * QSTR + ks * 16) * 2));
            #pragma unroll
            for (int np = 0; np < 2; np++)
                LDSM_X4_T(bf[np*2][0], bf[np*2][1], bf[np*2+1][0], bf[np*2+1][1],
                          vB + (uint32_t)((ks * 16 * QSTR + np * 16) * 2));
            #pragma unroll
            for (int mt = 0; mt < 2; mt++)
                #pragma unroll
                for (int nt = 0; nt < 4; nt++)
                    mma_h(o[mt][nt], af[mt], bf[nt]);
        }
        __syncthreads();
    }

    // reduce row sums: quad shuffle then cross-(wn) via smem
    #pragma unroll
    for (int mt = 0; mt < 2; mt++)
        #pragma unroll
        for (int hh = 0; hh < 2; hh++) {
            float vv = rs[mt][hh];
            vv += __shfl_xor_sync(0xffffffffu, vv, 1);
            vv += __shfl_xor_sync(0xffffffffu, vv, 2);
            rs[mt][hh] = vv;
        }
    if (tg == 0) {
        #pragma unroll
        for (int mt = 0; mt < 2; mt++) {
            sm.lsum[wm*32 + mt*16 + g][wn]     = rs[mt][0];
            sm.lsum[wm*32 + mt*16 + g + 8][wn] = rs[mt][1];
        }
    }
    __syncthreads();

    // normalize + scatter into scrambled layout:
    // [b,h,s,dh] -> ao[b][2c + (s>>10)][s & 1023], c = h*64+dh
    #pragma unroll
    for (int mt = 0; mt < 2; mt++) {
        float inv[2];
        #pragma unroll
        for (int h2 = 0; h2 < 2; h2++) {
            int lr = wm*32 + mt*16 + g + h2*8;
            inv[h2] = 1.0f / (sm.lsum[lr][0] + sm.lsum[lr][1]);
        }
        #pragma unroll
        for (int nt = 0; nt < 4; nt++) {
            #pragma unroll
            for (int h2 = 0; h2 < 2; h2++) {
                int sgl = q0 + wm*32 + mt*16 + g + h2*8;
                #pragma unroll
                for (int c2 = 0; c2 < 2; c2++) {
                    int dh = wn*32 + nt*8 + tg*2 + c2;
                    int c  = h * 64 + dh;
                    size_t idx = (size_t)b * SEQ * DIM
                               + (size_t)(2*c + (sgl >> 10)) * DIM + (sgl & 1023);
                    ao[idx] = o[mt][nt][h2*2 + c2] * inv[h2];
                }
            }
        }
    }
}

// ---------------------------------------------------------------------------
extern "C" void kernel_launch(void* const* d_in, const int* in_sizes, int n_in,
                              void* d_out, int out_size)
{
    const float* x  = (const float*)d_in[0];
    const float* Wq = (const float*)d_in[2];
    const float* bq = (const float*)d_in[3];
    const float* Wk = (const float*)d_in[4];
    const float* bk = (const float*)d_in[5];
    const float* Wv = (const float*)d_in[6];
    const float* bv = (const float*)d_in[7];
    const float* Wo = (const float*)d_in[8];
    const float* bo = (const float*)d_in[9];
    float* out = (float*)d_out;

    __half *q, *k, *v;
    float *ao;
    cudaGetSymbolAddress((void**)&q,  g_q);
    cudaGetSymbolAddress((void**)&k,  g_k);
    cudaGetSymbolAddress((void**)&v,  g_v);
    cudaGetSymbolAddress((void**)&ao, g_ao);

    // fused QKV projections (z = 0,1,2)
    dim3 gg(DIM / 128, MTOT / 128, 3);   // (8, 32, 3)
    gemm_h<<<gg, 256>>>(x, Wq, Wk, Wv, bq, bk, bv, q, k, v, nullptr, 0);

    dim3 ga(SEQ / 64, BATCH * HEADS);    // (32, 32)
    attn_h<<<ga, 128>>>(q, k, v, ao);

    // output projection (f32 out)
    dim3 go(DIM / 128, MTOT / 128, 1);
    gemm_h<<<go, 256>>>(ao, Wo, Wo, Wo, bo, bo, bo, q, q, q, out, 1);
}

// round 6
// speedup vs baseline: 9.3956x; 1.1991x over previous
#include <cuda_runtime.h>
#include <cuda_fp16.h>
#include <cstdint>

#define BATCH 2
#define HEADS 16
#define SEQ   2048
#define DIM   1024
#define HDIM  64
#define MTOT  (BATCH*SEQ)   // 4096
#define SCALE 0.125f

// Scratch (device globals: allocation-free rule)
__device__ __half g_xh[MTOT*DIM];              // x in fp16
__device__ __half g_wh[4*DIM*DIM];             // Wq|Wk|Wv|Wo in fp16
__device__ __half g_q[BATCH*HEADS*SEQ*HDIM];   // [b,h,s,dh]
__device__ __half g_k[BATCH*HEADS*SEQ*HDIM];
__device__ __half g_v[BATCH*HEADS*SEQ*HDIM];
__device__ __half g_aoh[MTOT*DIM];             // scrambled attn output (fp16)

// ---------------------------------------------------------------------------
// helpers
// ---------------------------------------------------------------------------
__device__ __forceinline__ uint32_t smem_u32(const void* p) {
    uint32_t a;
    asm("{ .reg .u64 t; cvta.to.shared.u64 t, %1; cvt.u32.u64 %0, t; }"
        : "=r"(a) : "l"(p));
    return a;
}
#define LDSM_X4(r0,r1,r2,r3,addr) \
    asm volatile("ldmatrix.sync.aligned.m8n8.x4.shared.b16 {%0,%1,%2,%3}, [%4];" \
        : "=r"(r0),"=r"(r1),"=r"(r2),"=r"(r3) : "r"(addr))
#define LDSM_X4_T(r0,r1,r2,r3,addr) \
    asm volatile("ldmatrix.sync.aligned.m8n8.x4.trans.shared.b16 {%0,%1,%2,%3}, [%4];" \
        : "=r"(r0),"=r"(r1),"=r"(r2),"=r"(r3) : "r"(addr))
#define CP16(smem, gptr) \
    asm volatile("cp.async.cg.shared.global [%0], [%1], 16;" :: "r"(smem), "l"(gptr))
#define CP_COMMIT() asm volatile("cp.async.commit_group;")
#define CP_WAIT(n)  asm volatile("cp.async.wait_group %0;" :: "n"(n))

__device__ __forceinline__ void mma_h(float c[4], const uint32_t a[4], const uint32_t b[2]) {
    asm volatile(
        "mma.sync.aligned.m16n8k16.row.col.f32.f16.f16.f32 "
        "{%0,%1,%2,%3}, {%4,%5,%6,%7}, {%8,%9}, {%0,%1,%2,%3};"
        : "+f"(c[0]), "+f"(c[1]), "+f"(c[2]), "+f"(c[3])
        : "r"(a[0]), "r"(a[1]), "r"(a[2]), "r"(a[3]), "r"(b[0]), "r"(b[1]));
}

// ---------------------------------------------------------------------------
// one-shot f32 -> fp16 conversion of x and the four weight matrices
// 8M elems, 8 per thread
// ---------------------------------------------------------------------------
__global__ __launch_bounds__(256) void convert_h(
    const float* __restrict__ x,
    const float* __restrict__ wq, const float* __restrict__ wk,
    const float* __restrict__ wv, const float* __restrict__ wo,
    __half* __restrict__ xh, __half* __restrict__ wh)
{
    size_t t = (size_t)blockIdx.x * 256 + threadIdx.x;
    size_t base = t * 8;
    unsigned seg = (unsigned)(base >> 20);
    const float* src;
    __half* dst;
    if (seg < 4) { src = x + base; dst = xh + base; }
    else {
        size_t off = base - ((size_t)seg << 20);
        const float* w = (seg == 4) ? wq : (seg == 5) ? wk : (seg == 6) ? wv : wo;
        src = w + off;
        dst = wh + (base - ((size_t)4 << 20));
    }
    float4 a = *(const float4*)src;
    float4 b = *(const float4*)(src + 4);
    __half2 h[4] = {__floats2half2_rn(a.x, a.y), __floats2half2_rn(a.z, a.w),
                    __floats2half2_rn(b.x, b.y), __floats2half2_rn(b.z, b.w)};
    *(uint4*)dst = *(uint4*)h;
}

// ---------------------------------------------------------------------------
// fp16 GEMM (cp.async 3-stage): C = A(fp16) @ W^T(fp16) + bias
// Tile 128x128, BK=64, 256 threads, warps 2x4 (64x32 each)
// mode 0: scatter fp16 into [b,h,s,dh]; mode 1: f32 row-major.
// ---------------------------------------------------------------------------
#define BK     64
#define GST    72                  // halves per smem row (64 + 8 pad) = 144B
#define GSTAGE (128*GST)           // halves per operand per stage
#define GSMEM  (6*GSTAGE*2)        // bytes: 3 stages x (A+W)

__global__ __launch_bounds__(256, 2) void gemm_h(
    const __half* __restrict__ A, const __half* __restrict__ Wb,
    const float* __restrict__ B0, const float* __restrict__ B1, const float* __restrict__ B2,
    __half* __restrict__ H0, __half* __restrict__ H1, __half* __restrict__ H2,
    float* __restrict__ Cf, int mode)
{
    extern __shared__ __half smg[];
    __half* As = smg;
    __half* Ws = smg + 3 * GSTAGE;

    const int z = blockIdx.z;
    const __half* W = Wb + (size_t)z * (DIM * DIM);
    const float* Bi = (z == 0) ? B0 : ((z == 1) ? B1 : B2);
    __half* Ho      = (z == 0) ? H0 : ((z == 1) ? H1 : H2);

    const int tid = threadIdx.x, lane = tid & 31, wid = tid >> 5;
    const int g = lane >> 2, tg = lane & 3;
    const int m0 = blockIdx.y * 128, n0 = blockIdx.x * 128;
    const int wm0 = (wid >> 2) * 64, wn0 = (wid & 3) * 32;

    float acc[4][4][4];
    #pragma unroll
    for (int mt = 0; mt < 4; mt++)
        #pragma unroll
        for (int nt = 0; nt < 4; nt++)
            #pragma unroll
            for (int r = 0; r < 4; r++) acc[mt][nt][r] = 0.f;

    const uint32_t aBase = smem_u32(As), wBase = smem_u32(Ws);
    const int ldRow = tid >> 3, ldCc = (tid & 7) * 8;

    auto load_stage = [&](int st, int kb) {
        const __half* Ag = A + (size_t)m0 * DIM + kb * BK;
        const __half* Wg = W + (size_t)n0 * DIM + kb * BK;
        uint32_t sa = aBase + (uint32_t)(st * GSTAGE) * 2;
        uint32_t sw = wBase + (uint32_t)(st * GSTAGE) * 2;
        #pragma unroll
        for (int i = 0; i < 4; i++) {
            int row = ldRow + i * 32;
            uint32_t so = (uint32_t)(row * GST + ldCc) * 2;
            CP16(sa + so, Ag + (size_t)row * DIM + ldCc);
            CP16(sw + so, Wg + (size_t)row * DIM + ldCc);
        }
        CP_COMMIT();
    };

    // ldmatrix lane addresses (bytes)
    const uint32_t aLane = (uint32_t)(((wm0 + (lane & 15)) * GST + (lane >> 4) * 8) * 2);
    const int bRow = (lane & 7) + ((lane & 16) ? 8 : 0);
    const int bColH = (lane & 8) ? 8 : 0;
    const uint32_t bLane = (uint32_t)(((wn0 + bRow) * GST + bColH) * 2);
    const uint32_t stageB = (uint32_t)GSTAGE * 2;

    load_stage(0, 0);
    load_stage(1, 1);

    const int NKB = DIM / BK;   // 16
    for (int kb = 0; kb < NKB; kb++) {
        const int cur = kb % 3;
        if (kb == NKB - 1) { CP_WAIT(0); } else { CP_WAIT(1); }
        __syncthreads();
        if (kb + 2 < NKB) load_stage((kb + 2) % 3, kb + 2);

        const uint32_t aS = aBase + cur * stageB + aLane;
        const uint32_t bS = wBase + cur * stageB + bLane;
        #pragma unroll
        for (int ks = 0; ks < 4; ks++) {
            uint32_t af[4][4], bf[4][2];
            #pragma unroll
            for (int mt = 0; mt < 4; mt++)
                LDSM_X4(af[mt][0], af[mt][1], af[mt][2], af[mt][3],
                        aS + (uint32_t)((mt * 16 * GST + ks * 16) * 2));
            #pragma unroll
            for (int np = 0; np < 2; np++)
                LDSM_X4(bf[np*2][0], bf[np*2][1], bf[np*2+1][0], bf[np*2+1][1],
                        bS + (uint32_t)((np * 16 * GST + ks * 16) * 2));
            #pragma unroll
            for (int mt = 0; mt < 4; mt++)
                #pragma unroll
                for (int nt = 0; nt < 4; nt++)
                    mma_h(acc[mt][nt], af[mt], bf[nt]);
        }
        __syncthreads();
    }

    // epilogue
    #pragma unroll
    for (int mt = 0; mt < 4; mt++) {
        #pragma unroll
        for (int nt = 0; nt < 4; nt++) {
            int col = n0 + wn0 + nt * 8 + tg * 2;
            float b0v = Bi[col], b1v = Bi[col + 1];
            #pragma unroll
            for (int h2 = 0; h2 < 2; h2++) {
                int row = m0 + wm0 + mt * 16 + g + h2 * 8;
                float v0 = acc[mt][nt][h2*2 + 0] + b0v;
                float v1 = acc[mt][nt][h2*2 + 1] + b1v;
                if (mode == 0) {
                    int b = row >> 11, s = row & 2047;
                    int hh = col >> 6, dh = col & 63;
                    size_t idx = (((size_t)(b * HEADS + hh)) * SEQ + s) * HDIM + dh;
                    *(__half2*)(Ho + idx) = __floats2half2_rn(v0, v1);
                } else {
                    *(float2*)(Cf + (size_t)row * DIM + col) = make_float2(v0, v1);
                }
            }
        }
    }
}

// ---------------------------------------------------------------------------
// fp16 attention, cp.async double-buffered K/V, 128-query CTAs.
// Dense softmax (mask=-1e-9 => exp==1.0f): no max, no rescale.
// 256 threads, warps 4x2 (each 32 rows x 32 cols). Output fp16, scattered.
// smem halves layout: Q[128][72] | P[128][72] | K[2][64][72] | V[2][64][72] | lsum
// ---------------------------------------------------------------------------
#define AST     72
#define AQ_OFF  0
#define AP_OFF  (128*AST)
#define AK_OFF  (2*128*AST)
#define AV_OFF  (AK_OFF + 2*64*AST)
#define AH_TOT  (AV_OFF + 2*64*AST)           // halves
#define ASMEM   (AH_TOT*2 + 128*2*4)          // + lsum floats

__global__ __launch_bounds__(256, 2) void attn_h(
    const __half* __restrict__ q, const __half* __restrict__ k,
    const __half* __restrict__ v, __half* __restrict__ ao)
{
    extern __shared__ __half sma[];
    float* lsum = (float*)(sma + AH_TOT);

    const int tid = threadIdx.x, lane = tid & 31, wid = tid >> 5;
    const int g = lane >> 2, tg = lane & 3;
    const int wm = wid >> 1, wn = wid & 1;
    const int bh = blockIdx.y, b = bh >> 4, h = bh & 15;
    const int q0 = blockIdx.x * 128;

    const __half* qp = q + (size_t)bh * SEQ * HDIM;
    const __half* kp = k + (size_t)bh * SEQ * HDIM;
    const __half* vp = v + (size_t)bh * SEQ * HDIM;

    const uint32_t sBase = smem_u32(sma);

    // K/V stage loader: 512 K-chunks + 512 V-chunks, 4 per thread
    const int kvRow = tid >> 3, kvCc = (tid & 7) * 8;
    auto load_kv = [&](int st, int kt) {
        const __half* Kg = kp + (size_t)(kt * 64) * HDIM;
        const __half* Vg = vp + (size_t)(kt * 64) * HDIM;
        uint32_t sk = sBase + (uint32_t)(AK_OFF + st * 64 * AST) * 2;
        uint32_t sv = sBase + (uint32_t)(AV_OFF + st * 64 * AST) * 2;
        #pragma unroll
        for (int i = 0; i < 2; i++) {
            int row = kvRow + i * 32;
            uint32_t so = (uint32_t)(row * AST + kvCc) * 2;
            CP16(sk + so, Kg + (size_t)row * HDIM + kvCc);
            CP16(sv + so, Vg + (size_t)row * HDIM + kvCc);
        }
        CP_COMMIT();
    };

    // prologue: full Q tile (128 rows x 64 halves; 4 chunks/thread) + first K/V
    {
        const int row = tid >> 1, cc = (tid & 1) * 32;
        #pragma unroll
        for (int i = 0; i < 4; i++) {
            uint32_t so = sBase + (uint32_t)(AQ_OFF + row * AST + cc + i * 8) * 2;
            CP16(so, qp + (size_t)(q0 + row) * HDIM + cc + i * 8);
        }
        uint32_t sk = sBase + (uint32_t)AK_OFF * 2;
        uint32_t sv = sBase + (uint32_t)AV_OFF * 2;
        #pragma unroll
        for (int i = 0; i < 2; i++) {
            int rowk = kvRow + i * 32;
            uint32_t so = (uint32_t)(rowk * AST + kvCc) * 2;
            CP16(sk + so, kp + (size_t)rowk * HDIM + kvCc);
            CP16(sv + so, vp + (size_t)rowk * HDIM + kvCc);
        }
        CP_COMMIT();
    }

    float o[2][4][4];
    float rs[2][2] = {{0.f, 0.f}, {0.f, 0.f}};
    #pragma unroll
    for (int mt = 0; mt < 2; mt++)
        #pragma unroll
        for (int nt = 0; nt < 4; nt++)
            #pragma unroll
            for (int r = 0; r < 4; r++) o[mt][nt][r] = 0.f;

    // ldmatrix lane addresses (bytes)
    const uint32_t qA = sBase + (uint32_t)((AQ_OFF + (wm*32 + (lane & 15)) * AST + (lane >> 4) * 8) * 2);
    const uint32_t pA = sBase + (uint32_t)((AP_OFF + (wm*32 + (lane & 15)) * AST + (lane >> 4) * 8) * 2);
    const int bRow = (lane & 7) + ((lane & 16) ? 8 : 0);
    const int bColH = (lane & 8) ? 8 : 0;
    const uint32_t kB0 = sBase + (uint32_t)((AK_OFF + (wn*32 + bRow) * AST + bColH) * 2);
    const int vRow = (lane & 7) + ((lane & 8) ? 8 : 0);
    const int vColH = (lane & 16) ? 8 : 0;
    const uint32_t vB0 = sBase + (uint32_t)((AV_OFF + vRow * AST + wn*32 + vColH) * 2);
    const uint32_t stB = (uint32_t)(64 * AST * 2);

    for (int kt = 0; kt < 32; kt++) {
        const int cur = kt & 1;
        const int k0t = kt * 64;
        CP_WAIT(0);
        __syncthreads();
        if (kt + 1 < 32) load_kv(cur ^ 1, kt + 1);

        // S = Q @ K^T
        float s[2][4][4];
        #pragma unroll
        for (int mt = 0; mt < 2; mt++)
            #pragma unroll
            for (int nt = 0; nt < 4; nt++)
                #pragma unroll
                for (int r = 0; r < 4; r++) s[mt][nt][r] = 0.f;
        {
            const uint32_t kB = kB0 + cur * stB;
            #pragma unroll
            for (int ks = 0; ks < 4; ks++) {
                uint32_t af[2][4], bf[4][2];
                #pragma unroll
                for (int mt = 0; mt < 2; mt++)
                    LDSM_X4(af[mt][0], af[mt][1], af[mt][2], af[mt][3],
                            qA + (uint32_t)((mt * 16 * AST + ks * 16) * 2));
                #pragma unroll
                for (int np = 0; np < 2; np++)
                    LDSM_X4(bf[np*2][0], bf[np*2][1], bf[np*2+1][0], bf[np*2+1][1],
                            kB + (uint32_t)((np * 16 * AST + ks * 16) * 2));
                #pragma unroll
                for (int mt = 0; mt < 2; mt++)
                    #pragma unroll
                    for (int nt = 0; nt < 4; nt++)
                        mma_h(s[mt][nt], af[mt], bf[nt]);
            }
        }

        // mask + exp + row-sum partials + store P (fp16)
        #pragma unroll
        for (int mt = 0; mt < 2; mt++) {
            int rowg = q0 + wm*32 + mt*16 + g;
            #pragma unroll
            for (int nt = 0; nt < 4; nt++) {
                int colj = k0t + wn*32 + nt*8 + tg*2;
                float p0 = (colj     > rowg    ) ? 1.f : __expf(s[mt][nt][0] * SCALE);
                float p1 = (colj + 1 > rowg    ) ? 1.f : __expf(s[mt][nt][1] * SCALE);
                float p2 = (colj     > rowg + 8) ? 1.f : __expf(s[mt][nt][2] * SCALE);
                float p3 = (colj + 1 > rowg + 8) ? 1.f : __expf(s[mt][nt][3] * SCALE);
                rs[mt][0] += p0 + p1;
                rs[mt][1] += p2 + p3;
                int lr = wm*32 + mt*16 + g, lc = wn*32 + nt*8 + tg*2;
                *(__half2*)&sma[AP_OFF + lr * AST + lc]       = __floats2half2_rn(p0, p1);
                *(__half2*)&sma[AP_OFF + (lr + 8) * AST + lc] = __floats2half2_rn(p2, p3);
            }
        }
        __syncthreads();

        // O += P @ V
        {
            const uint32_t vB = vB0 + cur * stB;
            #pragma unroll
            for (int ks = 0; ks < 4; ks++) {
                uint32_t af[2][4], bf[4][2];
                #pragma unroll
                for (int mt = 0; mt < 2; mt++)
                    LDSM_X4(af[mt][0], af[mt][1], af[mt][2], af[mt][3],
                            pA + (uint32_t)((mt * 16 * AST + ks * 16) * 2));
                #pragma unroll
                for (int np = 0; np < 2; np++)
                    LDSM_X4_T(bf[np*2][0], bf[np*2][1], bf[np*2+1][0], bf[np*2+1][1],
                              vB + (uint32_t)((ks * 16 * AST + np * 16) * 2));
                #pragma unroll
                for (int mt = 0; mt < 2; mt++)
                    #pragma unroll
                    for (int nt = 0; nt < 4; nt++)
                        mma_h(o[mt][nt], af[mt], bf[nt]);
            }
        }
    }

    // reduce row sums: quad shuffle then cross-(wn) via smem
    #pragma unroll
    for (int mt = 0; mt < 2; mt++)
        #pragma unroll
        for (int hh = 0; hh < 2; hh++) {
            float vv = rs[mt][hh];
            vv += __shfl_xor_sync(0xffffffffu, vv, 1);
            vv += __shfl_xor_sync(0xffffffffu, vv, 2);
            rs[mt][hh] = vv;
        }
    __syncthreads();
    if (tg == 0) {
        #pragma unroll
        for (int mt = 0; mt < 2; mt++) {
            lsum[(wm*32 + mt*16 + g) * 2 + wn]     = rs[mt][0];
            lsum[(wm*32 + mt*16 + g + 8) * 2 + wn] = rs[mt][1];
        }
    }
    __syncthreads();

    // normalize + scatter fp16 into scrambled layout:
    // [b,h,s,dh] -> ao[b][2c + (s>>10)][s & 1023], c = h*64+dh
    #pragma unroll
    for (int mt = 0; mt < 2; mt++) {
        float inv[2];
        #pragma unroll
        for (int h2 = 0; h2 < 2; h2++) {
            int lr = wm*32 + mt*16 + g + h2*8;
            inv[h2] = 1.0f / (lsum[lr*2 + 0] + lsum[lr*2 + 1]);
        }
        #pragma unroll
        for (int nt = 0; nt < 4; nt++) {
            #pragma unroll
            for (int h2 = 0; h2 < 2; h2++) {
                int sgl = q0 + wm*32 + mt*16 + g + h2*8;
                #pragma unroll
                for (int c2 = 0; c2 < 2; c2++) {
                    int dh = wn*32 + nt*8 + tg*2 + c2;
                    int c  = h * 64 + dh;
                    size_t idx = (size_t)b * SEQ * DIM
                               + (size_t)(2*c + (sgl >> 10)) * DIM + (sgl & 1023);
                    ao[idx] = __float2half(o[mt][nt][h2*2 + c2] * inv[h2]);
                }
            }
        }
    }
}

// ---------------------------------------------------------------------------
extern "C" void kernel_launch(void* const* d_in, const int* in_sizes, int n_in,
                              void* d_out, int out_size)
{
    const float* x  = (const float*)d_in[0];
    const float* Wq = (const float*)d_in[2];
    const float* bq = (const float*)d_in[3];
    const float* Wk = (const float*)d_in[4];
    const float* bk = (const float*)d_in[5];
    const float* Wv = (const float*)d_in[6];
    const float* bv = (const float*)d_in[7];
    const float* Wo = (const float*)d_in[8];
    const float* bo = (const float*)d_in[9];
    float* out = (float*)d_out;

    __half *xh, *wh, *q, *k, *v, *aoh;
    cudaGetSymbolAddress((void**)&xh,  g_xh);
    cudaGetSymbolAddress((void**)&wh,  g_wh);
    cudaGetSymbolAddress((void**)&q,   g_q);
    cudaGetSymbolAddress((void**)&k,   g_k);
    cudaGetSymbolAddress((void**)&v,   g_v);
    cudaGetSymbolAddress((void**)&aoh, g_aoh);

    cudaFuncSetAttribute(gemm_h, cudaFuncAttributeMaxDynamicSharedMemorySize, GSMEM);
    cudaFuncSetAttribute(attn_h, cudaFuncAttributeMaxDynamicSharedMemorySize, ASMEM);

    // one-shot fp16 conversion of x + Wq/Wk/Wv/Wo
    convert_h<<<4096, 256>>>(x, Wq, Wk, Wv, Wo, xh, wh);

    // fused QKV projections
    dim3 gg(DIM / 128, MTOT / 128, 3);   // (8, 32, 3)
    gemm_h<<<gg, 256, GSMEM>>>(xh, wh, bq, bk, bv, q, k, v, nullptr, 0);

    dim3 ga(SEQ / 128, BATCH * HEADS);   // (16, 32)
    attn_h<<<ga, 256, ASMEM>>>(q, k, v, aoh);

    // output projection (f32 out), W = wh + 3*DIM*DIM
    dim3 go(DIM / 128, MTOT / 128, 1);
    gemm_h<<<go, 256, GSMEM>>>(aoh, wh + 3 * (size_t)DIM * DIM,
                               bo, bo, bo, q, q, q, out, 1);
}

// round 7
// speedup vs baseline: 10.3647x; 1.1032x over previous
#include <cuda_runtime.h>
#include <cuda_fp16.h>
#include <cstdint>

#define BATCH 2
#define HEADS 16
#define SEQ   2048
#define DIM   1024
#define HDIM  64
#define MTOT  (BATCH*SEQ)   // 4096
#define SCALE 0.125f

// Scratch (device globals: allocation-free rule)
__device__ __half g_xh[MTOT*DIM];              // x in fp16
__device__ __half g_wh[4*DIM*DIM];             // Wq|Wk|Wv|Wo in fp16
__device__ __half g_q[BATCH*HEADS*SEQ*HDIM];   // [b,h,s,dh]
__device__ __half g_k[BATCH*HEADS*SEQ*HDIM];
__device__ __half g_v[BATCH*HEADS*SEQ*HDIM];
__device__ __half g_aoh[MTOT*DIM];             // scrambled attn output (fp16)

// ---------------------------------------------------------------------------
// helpers
// ---------------------------------------------------------------------------
__device__ __forceinline__ uint32_t smem_u32(const void* p) {
    uint32_t a;
    asm("{ .reg .u64 t; cvta.to.shared.u64 t, %1; cvt.u32.u64 %0, t; }"
        : "=r"(a) : "l"(p));
    return a;
}
#define LDSM_X4(r0,r1,r2,r3,addr) \
    asm volatile("ldmatrix.sync.aligned.m8n8.x4.shared.b16 {%0,%1,%2,%3}, [%4];" \
        : "=r"(r0),"=r"(r1),"=r"(r2),"=r"(r3) : "r"(addr))
#define LDSM_X4_T(r0,r1,r2,r3,addr) \
    asm volatile("ldmatrix.sync.aligned.m8n8.x4.trans.shared.b16 {%0,%1,%2,%3}, [%4];" \
        : "=r"(r0),"=r"(r1),"=r"(r2),"=r"(r3) : "r"(addr))
#define CP16(smem, gptr) \
    asm volatile("cp.async.cg.shared.global [%0], [%1], 16;" :: "r"(smem), "l"(gptr))
#define CP_COMMIT() asm volatile("cp.async.commit_group;")
#define CP_WAIT(n)  asm volatile("cp.async.wait_group %0;" :: "n"(n))

__device__ __forceinline__ void mma_h(float c[4], const uint32_t a[4], const uint32_t b[2]) {
    asm volatile(
        "mma.sync.aligned.m16n8k16.row.col.f32.f16.f16.f32 "
        "{%0,%1,%2,%3}, {%4,%5,%6,%7}, {%8,%9}, {%0,%1,%2,%3};"
        : "+f"(c[0]), "+f"(c[1]), "+f"(c[2]), "+f"(c[3])
        : "r"(a[0]), "r"(a[1]), "r"(a[2]), "r"(a[3]), "r"(b[0]), "r"(b[1]));
}
__device__ __forceinline__ uint32_t packh2(float a, float b) {
    __half2 h = __floats2half2_rn(a, b);
    return *(uint32_t*)&h;
}

// ---------------------------------------------------------------------------
// one-shot f32 -> fp16 conversion of x and the four weight matrices
// ---------------------------------------------------------------------------
__global__ __launch_bounds__(256) void convert_h(
    const float* __restrict__ x,
    const float* __restrict__ wq, const float* __restrict__ wk,
    const float* __restrict__ wv, const float* __restrict__ wo,
    __half* __restrict__ xh, __half* __restrict__ wh)
{
    size_t t = (size_t)blockIdx.x * 256 + threadIdx.x;
    size_t base = t * 8;
    unsigned seg = (unsigned)(base >> 20);
    const float* src;
    __half* dst;
    if (seg < 4) { src = x + base; dst = xh + base; }
    else {
        size_t off = base - ((size_t)seg << 20);
        const float* w = (seg == 4) ? wq : (seg == 5) ? wk : (seg == 6) ? wv : wo;
        src = w + off;
        dst = wh + (base - ((size_t)4 << 20));
    }
    float4 a = *(const float4*)src;
    float4 b = *(const float4*)(src + 4);
    __half2 h[4] = {__floats2half2_rn(a.x, a.y), __floats2half2_rn(a.z, a.w),
                    __floats2half2_rn(b.x, b.y), __floats2half2_rn(b.z, b.w)};
    *(uint4*)dst = *(uint4*)h;
}

// ---------------------------------------------------------------------------
// fp16 GEMM (cp.async 3-stage): C = A(fp16) @ W^T(fp16) + bias
// CTA tile 128x256, BK=64, 256 threads, 8 warps 2x4 (warp tile 64x64)
// mode 0: scatter fp16 into [b,h,s,dh]; mode 1: f32 row-major.
// ---------------------------------------------------------------------------
#define BK     64
#define GST    72                   // halves per smem row (64 + 8 pad)
#define GASTG  (128*GST)            // A stage halves
#define GBSTG  (256*GST)            // B stage halves
#define GSMEM  ((3*(GASTG+GBSTG))*2)

__global__ __launch_bounds__(256) void gemm_h(
    const __half* __restrict__ A, const __half* __restrict__ Wb,
    const float* __restrict__ B0, const float* __restrict__ B1, const float* __restrict__ B2,
    __half* __restrict__ H0, __half* __restrict__ H1, __half* __restrict__ H2,
    float* __restrict__ Cf, int mode)
{
    extern __shared__ __half smg[];
    __half* As = smg;
    __half* Ws = smg + 3 * GASTG;

    const int z = blockIdx.z;
    const __half* W = Wb + (size_t)z * (DIM * DIM);
    const float* Bi = (z == 0) ? B0 : ((z == 1) ? B1 : B2);
    __half* Ho      = (z == 0) ? H0 : ((z == 1) ? H1 : H2);

    const int tid = threadIdx.x, lane = tid & 31, wid = tid >> 5;
    const int g = lane >> 2, tg = lane & 3;
    const int m0 = blockIdx.y * 128, n0 = blockIdx.x * 256;
    const int wm0 = (wid >> 2) * 64, wn0 = (wid & 3) * 64;

    float acc[4][8][4];
    #pragma unroll
    for (int mt = 0; mt < 4; mt++)
        #pragma unroll
        for (int nt = 0; nt < 8; nt++)
            #pragma unroll
            for (int r = 0; r < 4; r++) acc[mt][nt][r] = 0.f;

    const uint32_t aBase = smem_u32(As), wBase = smem_u32(Ws);
    const int ldRow = tid >> 3, ldCc = (tid & 7) * 8;

    auto load_stage = [&](int st, int kb) {
        const __half* Ag = A + (size_t)m0 * DIM + kb * BK;
        const __half* Wg = W + (size_t)n0 * DIM + kb * BK;
        uint32_t sa = aBase + (uint32_t)(st * GASTG) * 2;
        uint32_t sw = wBase + (uint32_t)(st * GBSTG) * 2;
        #pragma unroll
        for (int i = 0; i < 4; i++) {
            int row = ldRow + i * 32;
            CP16(sa + (uint32_t)(row * GST + ldCc) * 2, Ag + (size_t)row * DIM + ldCc);
        }
        #pragma unroll
        for (int i = 0; i < 8; i++) {
            int row = ldRow + i * 32;
            CP16(sw + (uint32_t)(row * GST + ldCc) * 2, Wg + (size_t)row * DIM + ldCc);
        }
        CP_COMMIT();
    };

    // ldmatrix lane addresses (bytes)
    const uint32_t aLane = (uint32_t)(((wm0 + (lane & 15)) * GST + (lane >> 4) * 8) * 2);
    const int bRow = (lane & 7) + ((lane & 16) ? 8 : 0);
    const int bColH = (lane & 8) ? 8 : 0;
    const uint32_t bLane = (uint32_t)(((wn0 + bRow) * GST + bColH) * 2);
    const uint32_t aStB = (uint32_t)GASTG * 2, bStB = (uint32_t)GBSTG * 2;

    load_stage(0, 0);
    load_stage(1, 1);

    const int NKB = DIM / BK;   // 16
    for (int kb = 0; kb < NKB; kb++) {
        const int cur = kb % 3;
        if (kb == NKB - 1) { CP_WAIT(0); } else { CP_WAIT(1); }
        __syncthreads();
        if (kb + 2 < NKB) load_stage((kb + 2) % 3, kb + 2);

        const uint32_t aS = aBase + cur * aStB + aLane;
        const uint32_t bS = wBase + cur * bStB + bLane;
        #pragma unroll
        for (int ks = 0; ks < 4; ks++) {
            uint32_t af[4][4], bf[8][2];
            #pragma unroll
            for (int mt = 0; mt < 4; mt++)
                LDSM_X4(af[mt][0], af[mt][1], af[mt][2], af[mt][3],
                        aS + (uint32_t)((mt * 16 * GST + ks * 16) * 2));
            #pragma unroll
            for (int np = 0; np < 4; np++)
                LDSM_X4(bf[np*2][0], bf[np*2][1], bf[np*2+1][0], bf[np*2+1][1],
                        bS + (uint32_t)((np * 16 * GST + ks * 16) * 2));
            #pragma unroll
            for (int mt = 0; mt < 4; mt++)
                #pragma unroll
                for (int nt = 0; nt < 8; nt++)
                    mma_h(acc[mt][nt], af[mt], bf[nt]);
        }
        __syncthreads();
    }

    // epilogue
    #pragma unroll
    for (int mt = 0; mt < 4; mt++) {
        #pragma unroll
        for (int nt = 0; nt < 8; nt++) {
            int col = n0 + wn0 + nt * 8 + tg * 2;
            float b0v = Bi[col], b1v = Bi[col + 1];
            #pragma unroll
            for (int h2 = 0; h2 < 2; h2++) {
                int row = m0 + wm0 + mt * 16 + g + h2 * 8;
                float v0 = acc[mt][nt][h2*2 + 0] + b0v;
                float v1 = acc[mt][nt][h2*2 + 1] + b1v;
                if (mode == 0) {
                    int b = row >> 11, s = row & 2047;
                    int hh = col >> 6, dh = col & 63;
                    size_t idx = (((size_t)(b * HEADS + hh)) * SEQ + s) * HDIM + dh;
                    *(__half2*)(Ho + idx) = __floats2half2_rn(v0, v1);
                } else {
                    *(float2*)(Cf + (size_t)row * DIM + col) = make_float2(v0, v1);
                }
            }
        }
    }
}

// ---------------------------------------------------------------------------
// fp16 attention, register-resident P (no smem roundtrip), persistent Q frags.
// CTA: 128 queries x one (b,h), 256 threads, 8 warps; warp = 16 rows,
// full 64-key x 64-dh tile. One __syncthreads per tile.
// Dense softmax (mask=-1e-9 => exp==1.0f): no max, no rescale.
// smem halves: Q[128][72] | K[2][64][72] | V[2][64][72]
// ---------------------------------------------------------------------------
#define AST     72
#define AQ_OFF  0
#define AK_OFF  (128*AST)
#define AV_OFF  (AK_OFF + 2*64*AST)
#define AH_TOT  (AV_OFF + 2*64*AST)
#define ASMEM   (AH_TOT*2)

__global__ __launch_bounds__(256, 2) void attn_h(
    const __half* __restrict__ q, const __half* __restrict__ k,
    const __half* __restrict__ v, __half* __restrict__ ao)
{
    extern __shared__ __half sma[];

    const int tid = threadIdx.x, lane = tid & 31, wid = tid >> 5;
    const int g = lane >> 2, tg = lane & 3;
    const int bh = blockIdx.y, b = bh >> 4, h = bh & 15;
    const int q0 = blockIdx.x * 128;

    const __half* qp = q + (size_t)bh * SEQ * HDIM;
    const __half* kp = k + (size_t)bh * SEQ * HDIM;
    const __half* vp = v + (size_t)bh * SEQ * HDIM;

    const uint32_t sBase = smem_u32(sma);

    const int kvRow = tid >> 3, kvCc = (tid & 7) * 8;
    auto load_kv = [&](int st, int kt) {
        const __half* Kg = kp + (size_t)(kt * 64) * HDIM;
        const __half* Vg = vp + (size_t)(kt * 64) * HDIM;
        uint32_t sk = sBase + (uint32_t)(AK_OFF + st * 64 * AST) * 2;
        uint32_t sv = sBase + (uint32_t)(AV_OFF + st * 64 * AST) * 2;
        #pragma unroll
        for (int i = 0; i < 2; i++) {
            int row = kvRow + i * 32;
            uint32_t so = (uint32_t)(row * AST + kvCc) * 2;
            CP16(sk + so, Kg + (size_t)row * HDIM + kvCc);
            CP16(sv + so, Vg + (size_t)row * HDIM + kvCc);
        }
        CP_COMMIT();
    };

    // prologue: Q tile + K/V stage 0
    {
        const int row = tid >> 1, cc = (tid & 1) * 32;
        #pragma unroll
        for (int i = 0; i < 4; i++)
            CP16(sBase + (uint32_t)(AQ_OFF + row * AST + cc + i * 8) * 2,
                 qp + (size_t)(q0 + row) * HDIM + cc + i * 8);
        uint32_t sk = sBase + (uint32_t)AK_OFF * 2;
        uint32_t sv = sBase + (uint32_t)AV_OFF * 2;
        #pragma unroll
        for (int i = 0; i < 2; i++) {
            int rowk = kvRow + i * 32;
            uint32_t so = (uint32_t)(rowk * AST + kvCc) * 2;
            CP16(sk + so, kp + (size_t)rowk * HDIM + kvCc);
            CP16(sv + so, vp + (size_t)rowk * HDIM + kvCc);
        }
        CP_COMMIT();
    }

    CP_WAIT(0);
    __syncthreads();

    // persistent Q fragments: warp rows [wid*16, wid*16+16), 4 k-steps over dh
    uint32_t qf[4][4];
    {
        const uint32_t qA = sBase +
            (uint32_t)((AQ_OFF + (wid * 16 + (lane & 15)) * AST + (lane >> 4) * 8) * 2);
        #pragma unroll
        for (int ks = 0; ks < 4; ks++)
            LDSM_X4(qf[ks][0], qf[ks][1], qf[ks][2], qf[ks][3], qA + (uint32_t)(ks * 32));
    }

    load_kv(1, 1);

    float o[8][4];
    float rs0 = 0.f, rs1 = 0.f;
    #pragma unroll
    for (int nt = 0; nt < 8; nt++)
        #pragma unroll
        for (int r = 0; r < 4; r++) o[nt][r] = 0.f;

    // ldmatrix lane address components
    const int bRow = (lane & 7) + ((lane & 16) ? 8 : 0);
    const int bColH = (lane & 8) ? 8 : 0;
    const int vRow = (lane & 7) + ((lane & 8) ? 8 : 0);
    const int vColH = (lane & 16) ? 8 : 0;
    const uint32_t stB = (uint32_t)(64 * AST * 2);
    const uint32_t kB0 = sBase + (uint32_t)((AK_OFF + bRow * AST + bColH) * 2);
    const uint32_t vB0 = sBase + (uint32_t)((AV_OFF + vRow * AST + vColH) * 2);
    const int row0 = q0 + wid * 16 + g;

    for (int kt = 0; kt < 32; kt++) {
        const int cur = kt & 1;
        const int k0t = kt * 64;
        if (kt > 0) {
            CP_WAIT(0);
            __syncthreads();
            if (kt + 1 < 32) load_kv(cur ^ 1, kt + 1);
        }

        // S = Q @ K^T : warp rows x 64 keys
        float s[8][4];
        #pragma unroll
        for (int nt = 0; nt < 8; nt++)
            #pragma unroll
            for (int r = 0; r < 4; r++) s[nt][r] = 0.f;
        {
            const uint32_t kB = kB0 + cur * stB;
            #pragma unroll
            for (int ks = 0; ks < 4; ks++) {
                uint32_t bf[8][2];
                #pragma unroll
                for (int np = 0; np < 4; np++)
                    LDSM_X4(bf[np*2][0], bf[np*2][1], bf[np*2+1][0], bf[np*2+1][1],
                            kB + (uint32_t)((np * 16 * AST + ks * 16) * 2));
                #pragma unroll
                for (int nt = 0; nt < 8; nt++)
                    mma_h(s[nt], qf[ks], bf[nt]);
            }
        }

        // mask + exp -> PV A-fragments in registers + row-sum partials
        uint32_t pf[4][4];
        #pragma unroll
        for (int nt = 0; nt < 8; nt++) {
            int colj = k0t + nt * 8 + tg * 2;
            float p0 = (colj     > row0    ) ? 1.f : __expf(s[nt][0] * SCALE);
            float p1 = (colj + 1 > row0    ) ? 1.f : __expf(s[nt][1] * SCALE);
            float p2 = (colj     > row0 + 8) ? 1.f : __expf(s[nt][2] * SCALE);
            float p3 = (colj + 1 > row0 + 8) ? 1.f : __expf(s[nt][3] * SCALE);
            rs0 += p0 + p1;
            rs1 += p2 + p3;
            pf[nt >> 1][(nt & 1) * 2 + 0] = packh2(p0, p1);
            pf[nt >> 1][(nt & 1) * 2 + 1] = packh2(p2, p3);
        }

        // O += P @ V : keys in 4 chunks of 16, dh 64 wide
        {
            const uint32_t vB = vB0 + cur * stB;
            #pragma unroll
            for (int kp2 = 0; kp2 < 4; kp2++) {
                uint32_t vf[8][2];
                #pragma unroll
                for (int np = 0; np < 4; np++)
                    LDSM_X4_T(vf[np*2][0], vf[np*2][1], vf[np*2+1][0], vf[np*2+1][1],
                              vB + (uint32_t)((kp2 * 16 * AST + np * 16) * 2));
                #pragma unroll
                for (int nt = 0; nt < 8; nt++)
                    mma_h(o[nt], pf[kp2], vf[nt]);
            }
        }
    }

    // warp-local row-sum reduction over tg (lanes differ in bits 0-1)
    rs0 += __shfl_xor_sync(0xffffffffu, rs0, 1);
    rs0 += __shfl_xor_sync(0xffffffffu, rs0, 2);
    rs1 += __shfl_xor_sync(0xffffffffu, rs1, 1);
    rs1 += __shfl_xor_sync(0xffffffffu, rs1, 2);
    const float inv0 = 1.0f / rs0, inv1 = 1.0f / rs1;

    // normalize + scatter fp16 into scrambled layout:
    // [b,h,s,dh] -> ao[b][2c + (s>>10)][s & 1023], c = h*64+dh
    const int s0 = row0, s1 = row0 + 8;
    #pragma unroll
    for (int nt = 0; nt < 8; nt++) {
        #pragma unroll
        for (int c2 = 0; c2 < 2; c2++) {
            int dh = nt * 8 + tg * 2 + c2;
            int c  = h * 64 + dh;
            size_t rowb = (size_t)b * SEQ * DIM;
            ao[rowb + (size_t)(2*c + (s0 >> 10)) * DIM + (s0 & 1023)] =
                __float2half(o[nt][c2] * inv0);
            ao[rowb + (size_t)(2*c + (s1 >> 10)) * DIM + (s1 & 1023)] =
                __float2half(o[nt][2 + c2] * inv1);
        }
    }
}

// ---------------------------------------------------------------------------
extern "C" void kernel_launch(void* const* d_in, const int* in_sizes, int n_in,
                              void* d_out, int out_size)
{
    const float* x  = (const float*)d_in[0];
    const float* Wq = (const float*)d_in[2];
    const float* bq = (const float*)d_in[3];
    const float* Wk = (const float*)d_in[4];
    const float* bk = (const float*)d_in[5];
    const float* Wv = (const float*)d_in[6];
    const float* bv = (const float*)d_in[7];
    const float* Wo = (const float*)d_in[8];
    const float* bo = (const float*)d_in[9];
    float* out = (float*)d_out;

    __half *xh, *wh, *q, *k, *v, *aoh;
    cudaGetSymbolAddress((void**)&xh,  g_xh);
    cudaGetSymbolAddress((void**)&wh,  g_wh);
    cudaGetSymbolAddress((void**)&q,   g_q);
    cudaGetSymbolAddress((void**)&k,   g_k);
    cudaGetSymbolAddress((void**)&v,   g_v);
    cudaGetSymbolAddress((void**)&aoh, g_aoh);

    cudaFuncSetAttribute(gemm_h, cudaFuncAttributeMaxDynamicSharedMemorySize, GSMEM);
    cudaFuncSetAttribute(attn_h, cudaFuncAttributeMaxDynamicSharedMemorySize, ASMEM);

    // one-shot fp16 conversion of x + Wq/Wk/Wv/Wo
    convert_h<<<4096, 256>>>(x, Wq, Wk, Wv, Wo, xh, wh);

    // fused QKV projections (CTA tile 128x256)
    dim3 gg(DIM / 256, MTOT / 128, 3);   // (4, 32, 3)
    gemm_h<<<gg, 256, GSMEM>>>(xh, wh, bq, bk, bv, q, k, v, nullptr, 0);

    dim3 ga(SEQ / 128, BATCH * HEADS);   // (16, 32)
    attn_h<<<ga, 256, ASMEM>>>(q, k, v, aoh);

    // output projection (f32 out), W = wh + 3*DIM*DIM
    dim3 go(DIM / 256, MTOT / 128, 1);
    gemm_h<<<go, 256, GSMEM>>>(aoh, wh + 3 * (size_t)DIM * DIM,
                               bo, bo, bo, q, q, q, out, 1);
}

// round 8
// speedup vs baseline: 11.6138x; 1.1205x over previous
#include <cuda_runtime.h>
#include <cuda_fp16.h>
#include <cstdint>

#define BATCH 2
#define HEADS 16
#define SEQ   2048
#define DIM   1024
#define HDIM  64
#define MTOT  (BATCH*SEQ)   // 4096
#define SCALE 0.125f
#define NQB   (SEQ/128)     // 16 query blocks per (b,h)

// Scratch (device globals: allocation-free rule)
__device__ __half g_xh[MTOT*DIM];              // x in fp16
__device__ __half g_wh[4*DIM*DIM];             // Wq|Wk|Wv|Wo in fp16
__device__ __half g_q[BATCH*HEADS*SEQ*HDIM];   // [b,h,s,dh]
__device__ __half g_k[BATCH*HEADS*SEQ*HDIM];
__device__ __half g_v[BATCH*HEADS*SEQ*HDIM];
__device__ __half g_aoh[MTOT*DIM];             // scrambled attn output (fp16)
__device__ float  g_tsum[BATCH*HEADS*32*HDIM]; // per-tile V column sums

// ---------------------------------------------------------------------------
// helpers
// ---------------------------------------------------------------------------
__device__ __forceinline__ uint32_t smem_u32(const void* p) {
    uint32_t a;
    asm("{ .reg .u64 t; cvta.to.shared.u64 t, %1; cvt.u32.u64 %0, t; }"
        : "=r"(a) : "l"(p));
    return a;
}
#define LDSM_X4(r0,r1,r2,r3,addr) \
    asm volatile("ldmatrix.sync.aligned.m8n8.x4.shared.b16 {%0,%1,%2,%3}, [%4];" \
        : "=r"(r0),"=r"(r1),"=r"(r2),"=r"(r3) : "r"(addr))
#define LDSM_X4_T(r0,r1,r2,r3,addr) \
    asm volatile("ldmatrix.sync.aligned.m8n8.x4.trans.shared.b16 {%0,%1,%2,%3}, [%4];" \
        : "=r"(r0),"=r"(r1),"=r"(r2),"=r"(r3) : "r"(addr))
#define CP16(smem, gptr) \
    asm volatile("cp.async.cg.shared.global [%0], [%1], 16;" :: "r"(smem), "l"(gptr))
#define CP_COMMIT() asm volatile("cp.async.commit_group;")
#define CP_WAIT(n)  asm volatile("cp.async.wait_group %0;" :: "n"(n))

__device__ __forceinline__ void mma_h(float c[4], const uint32_t a[4], const uint32_t b[2]) {
    asm volatile(
        "mma.sync.aligned.m16n8k16.row.col.f32.f16.f16.f32 "
        "{%0,%1,%2,%3}, {%4,%5,%6,%7}, {%8,%9}, {%0,%1,%2,%3};"
        : "+f"(c[0]), "+f"(c[1]), "+f"(c[2]), "+f"(c[3])
        : "r"(a[0]), "r"(a[1]), "r"(a[2]), "r"(a[3]), "r"(b[0]), "r"(b[1]));
}
__device__ __forceinline__ uint32_t packh2(float a, float b) {
    __half2 h = __floats2half2_rn(a, b);
    return *(uint32_t*)&h;
}

// ---------------------------------------------------------------------------
// one-shot f32 -> fp16 conversion of x and the four weight matrices
// ---------------------------------------------------------------------------
__global__ __launch_bounds__(256) void convert_h(
    const float* __restrict__ x,
    const float* __restrict__ wq, const float* __restrict__ wk,
    const float* __restrict__ wv, const float* __restrict__ wo,
    __half* __restrict__ xh, __half* __restrict__ wh)
{
    size_t t = (size_t)blockIdx.x * 256 + threadIdx.x;
    size_t base = t * 8;
    unsigned seg = (unsigned)(base >> 20);
    const float* src;
    __half* dst;
    if (seg < 4) { src = x + base; dst = xh + base; }
    else {
        size_t off = base - ((size_t)seg << 20);
        const float* w = (seg == 4) ? wq : (seg == 5) ? wk : (seg == 6) ? wv : wo;
        src = w + off;
        dst = wh + (base - ((size_t)4 << 20));
    }
    float4 a = *(const float4*)src;
    float4 b = *(const float4*)(src + 4);
    __half2 h[4] = {__floats2half2_rn(a.x, a.y), __floats2half2_rn(a.z, a.w),
                    __floats2half2_rn(b.x, b.y), __floats2half2_rn(b.z, b.w)};
    *(uint4*)dst = *(uint4*)h;
}

// ---------------------------------------------------------------------------
// per-tile V column sums: T[bh][kt][dh] = sum over the 64 keys of tile kt
// ---------------------------------------------------------------------------
__global__ __launch_bounds__(64) void tilesum_k(
    const __half* __restrict__ v, float* __restrict__ T)
{
    const int kt = blockIdx.x, bh = blockIdx.y, dh = threadIdx.x;
    const __half* vp = v + ((size_t)bh * SEQ + kt * 64) * HDIM + dh;
    float acc = 0.f;
    #pragma unroll
    for (int j = 0; j < 64; j++) acc += __half2float(vp[(size_t)j * HDIM]);
    T[((size_t)bh * 32 + kt) * HDIM + dh] = acc;
}

// ---------------------------------------------------------------------------
// fp16 GEMM (cp.async 3-stage): C = A(fp16) @ W^T(fp16) + bias
// CTA tile 128x256, BK=64, 256 threads, 8 warps 2x4 (warp tile 64x64)
// mode 0: scatter fp16 into [b,h,s,dh]; mode 1: f32 row-major.
// ---------------------------------------------------------------------------
#define BK     64
#define GST    72
#define GASTG  (128*GST)
#define GBSTG  (256*GST)
#define GSMEM  ((3*(GASTG+GBSTG))*2)

__global__ __launch_bounds__(256) void gemm_h(
    const __half* __restrict__ A, const __half* __restrict__ Wb,
    const float* __restrict__ B0, const float* __restrict__ B1, const float* __restrict__ B2,
    __half* __restrict__ H0, __half* __restrict__ H1, __half* __restrict__ H2,
    float* __restrict__ Cf, int mode)
{
    extern __shared__ __half smg[];
    __half* As = smg;
    __half* Ws = smg + 3 * GASTG;

    const int z = blockIdx.z;
    const __half* W = Wb + (size_t)z * (DIM * DIM);
    const float* Bi = (z == 0) ? B0 : ((z == 1) ? B1 : B2);
    __half* Ho      = (z == 0) ? H0 : ((z == 1) ? H1 : H2);

    const int tid = threadIdx.x, lane = tid & 31, wid = tid >> 5;
    const int g = lane >> 2, tg = lane & 3;
    const int m0 = blockIdx.y * 128, n0 = blockIdx.x * 256;
    const int wm0 = (wid >> 2) * 64, wn0 = (wid & 3) * 64;

    float acc[4][8][4];
    #pragma unroll
    for (int mt = 0; mt < 4; mt++)
        #pragma unroll
        for (int nt = 0; nt < 8; nt++)
            #pragma unroll
            for (int r = 0; r < 4; r++) acc[mt][nt][r] = 0.f;

    const uint32_t aBase = smem_u32(As), wBase = smem_u32(Ws);
    const int ldRow = tid >> 3, ldCc = (tid & 7) * 8;

    auto load_stage = [&](int st, int kb) {
        const __half* Ag = A + (size_t)m0 * DIM + kb * BK;
        const __half* Wg = W + (size_t)n0 * DIM + kb * BK;
        uint32_t sa = aBase + (uint32_t)(st * GASTG) * 2;
        uint32_t sw = wBase + (uint32_t)(st * GBSTG) * 2;
        #pragma unroll
        for (int i = 0; i < 4; i++) {
            int row = ldRow + i * 32;
            CP16(sa + (uint32_t)(row * GST + ldCc) * 2, Ag + (size_t)row * DIM + ldCc);
        }
        #pragma unroll
        for (int i = 0; i < 8; i++) {
            int row = ldRow + i * 32;
            CP16(sw + (uint32_t)(row * GST + ldCc) * 2, Wg + (size_t)row * DIM + ldCc);
        }
        CP_COMMIT();
    };

    const uint32_t aLane = (uint32_t)(((wm0 + (lane & 15)) * GST + (lane >> 4) * 8) * 2);
    const int bRow = (lane & 7) + ((lane & 16) ? 8 : 0);
    const int bColH = (lane & 8) ? 8 : 0;
    const uint32_t bLane = (uint32_t)(((wn0 + bRow) * GST + bColH) * 2);
    const uint32_t aStB = (uint32_t)GASTG * 2, bStB = (uint32_t)GBSTG * 2;

    load_stage(0, 0);
    load_stage(1, 1);

    const int NKB = DIM / BK;   // 16
    for (int kb = 0; kb < NKB; kb++) {
        const int cur = kb % 3;
        if (kb == NKB - 1) { CP_WAIT(0); } else { CP_WAIT(1); }
        __syncthreads();
        if (kb + 2 < NKB) load_stage((kb + 2) % 3, kb + 2);

        const uint32_t aS = aBase + cur * aStB + aLane;
        const uint32_t bS = wBase + cur * bStB + bLane;
        #pragma unroll
        for (int ks = 0; ks < 4; ks++) {
            uint32_t af[4][4], bf[8][2];
            #pragma unroll
            for (int mt = 0; mt < 4; mt++)
                LDSM_X4(af[mt][0], af[mt][1], af[mt][2], af[mt][3],
                        aS + (uint32_t)((mt * 16 * GST + ks * 16) * 2));
            #pragma unroll
            for (int np = 0; np < 4; np++)
                LDSM_X4(bf[np*2][0], bf[np*2][1], bf[np*2+1][0], bf[np*2+1][1],
                        bS + (uint32_t)((np * 16 * GST + ks * 16) * 2));
            #pragma unroll
            for (int mt = 0; mt < 4; mt++)
                #pragma unroll
                for (int nt = 0; nt < 8; nt++)
                    mma_h(acc[mt][nt], af[mt], bf[nt]);
        }
        __syncthreads();
    }

    #pragma unroll
    for (int mt = 0; mt < 4; mt++) {
        #pragma unroll
        for (int nt = 0; nt < 8; nt++) {
            int col = n0 + wn0 + nt * 8 + tg * 2;
            float b0v = Bi[col], b1v = Bi[col + 1];
            #pragma unroll
            for (int h2 = 0; h2 < 2; h2++) {
                int row = m0 + wm0 + mt * 16 + g + h2 * 8;
                float v0 = acc[mt][nt][h2*2 + 0] + b0v;
                float v1 = acc[mt][nt][h2*2 + 1] + b1v;
                if (mode == 0) {
                    int b = row >> 11, s = row & 2047;
                    int hh = col >> 6, dh = col & 63;
                    size_t idx = (((size_t)(b * HEADS + hh)) * SEQ + s) * HDIM + dh;
                    *(__half2*)(Ho + idx) = __floats2half2_rn(v0, v1);
                } else {
                    *(float2*)(Cf + (size_t)row * DIM + col) = make_float2(v0, v1);
                }
            }
        }
    }
}

// ---------------------------------------------------------------------------
// fp16 attention with causal tile skipping.
// Fully-masked tiles (kt >= 2i+2) have P == 1.0 exactly -> contribution is
// the precomputed V column suffix sum; only tiles kt < 2i+2 are computed.
// CTA: 128 queries x one (b,h), 256 threads; warp = 16 rows x full 64x64 tile.
// smem halves: Q[128][72] | K[2][64][72] | V[2][64][72] | suf (64 floats)
// ---------------------------------------------------------------------------
#define AST     72
#define AQ_OFF  0
#define AK_OFF  (128*AST)
#define AV_OFF  (AK_OFF + 2*64*AST)
#define AH_TOT  (AV_OFF + 2*64*AST)
#define ASMEM   (AH_TOT*2 + 64*4)

__global__ __launch_bounds__(256, 2) void attn_h(
    const __half* __restrict__ q, const __half* __restrict__ k,
    const __half* __restrict__ v, const float* __restrict__ Tsum,
    __half* __restrict__ ao)
{
    extern __shared__ __half sma[];
    float* suf = (float*)(sma + AH_TOT);

    const int tid = threadIdx.x, lane = tid & 31, wid = tid >> 5;
    const int g = lane >> 2, tg = lane & 3;
    const int bh = blockIdx.y, b = bh >> 4, h = bh & 15;
    const int iq = (NQB - 1) - blockIdx.x;      // heavy blocks scheduled first
    const int q0 = iq * 128;
    const int ktEnd = 2 * iq + 2;               // tiles to compute (>=2)

    const __half* qp = q + (size_t)bh * SEQ * HDIM;
    const __half* kp = k + (size_t)bh * SEQ * HDIM;
    const __half* vp = v + (size_t)bh * SEQ * HDIM;

    const uint32_t sBase = smem_u32(sma);

    const int kvRow = tid >> 3, kvCc = (tid & 7) * 8;
    auto load_kv = [&](int st, int kt) {
        const __half* Kg = kp + (size_t)(kt * 64) * HDIM;
        const __half* Vg = vp + (size_t)(kt * 64) * HDIM;
        uint32_t sk = sBase + (uint32_t)(AK_OFF + st * 64 * AST) * 2;
        uint32_t sv = sBase + (uint32_t)(AV_OFF + st * 64 * AST) * 2;
        #pragma unroll
        for (int i = 0; i < 2; i++) {
            int row = kvRow + i * 32;
            uint32_t so = (uint32_t)(row * AST + kvCc) * 2;
            CP16(sk + so, Kg + (size_t)row * HDIM + kvCc);
            CP16(sv + so, Vg + (size_t)row * HDIM + kvCc);
        }
        CP_COMMIT();
    };

    // prologue: Q tile + K/V stage 0
    {
        const int row = tid >> 1, cc = (tid & 1) * 32;
        #pragma unroll
        for (int i = 0; i < 4; i++)
            CP16(sBase + (uint32_t)(AQ_OFF + row * AST + cc + i * 8) * 2,
                 qp + (size_t)(q0 + row) * HDIM + cc + i * 8);
        uint32_t sk = sBase + (uint32_t)AK_OFF * 2;
        uint32_t sv = sBase + (uint32_t)AV_OFF * 2;
        #pragma unroll
        for (int i = 0; i < 2; i++) {
            int rowk = kvRow + i * 32;
            uint32_t so = (uint32_t)(rowk * AST + kvCc) * 2;
            CP16(sk + so, kp + (size_t)rowk * HDIM + kvCc);
            CP16(sv + so, vp + (size_t)rowk * HDIM + kvCc);
        }
        CP_COMMIT();
    }

    // V column suffix sum over masked tiles (overlaps cp.async)
    if (tid < 64) {
        float acc = 0.f;
        const float* tp = Tsum + ((size_t)bh * 32) * HDIM + tid;
        for (int kt = ktEnd; kt < 32; kt++) acc += tp[(size_t)kt * HDIM];
        suf[tid] = acc;
    }

    CP_WAIT(0);
    __syncthreads();

    // persistent Q fragments
    uint32_t qf[4][4];
    {
        const uint32_t qA = sBase +
            (uint32_t)((AQ_OFF + (wid * 16 + (lane & 15)) * AST + (lane >> 4) * 8) * 2);
        #pragma unroll
        for (int ks = 0; ks < 4; ks++)
            LDSM_X4(qf[ks][0], qf[ks][1], qf[ks][2], qf[ks][3], qA + (uint32_t)(ks * 32));
    }

    load_kv(1, 1);

    float o[8][4];
    float rs0 = 0.f, rs1 = 0.f;
    #pragma unroll
    for (int nt = 0; nt < 8; nt++)
        #pragma unroll
        for (int r = 0; r < 4; r++) o[nt][r] = 0.f;

    const int bRow = (lane & 7) + ((lane & 16) ? 8 : 0);
    const int bColH = (lane & 8) ? 8 : 0;
    const int vRow = (lane & 7) + ((lane & 8) ? 8 : 0);
    const int vColH = (lane & 16) ? 8 : 0;
    const uint32_t stB = (uint32_t)(64 * AST * 2);
    const uint32_t kB0 = sBase + (uint32_t)((AK_OFF + bRow * AST + bColH) * 2);
    const uint32_t vB0 = sBase + (uint32_t)((AV_OFF + vRow * AST + vColH) * 2);
    const int row0 = q0 + wid * 16 + g;

    for (int kt = 0; kt < ktEnd; kt++) {
        const int cur = kt & 1;
        const int k0t = kt * 64;
        if (kt > 0) {
            CP_WAIT(0);
            __syncthreads();
            if (kt + 1 < ktEnd) load_kv(cur ^ 1, kt + 1);
        }

        // S = Q @ K^T
        float s[8][4];
        #pragma unroll
        for (int nt = 0; nt < 8; nt++)
            #pragma unroll
            for (int r = 0; r < 4; r++) s[nt][r] = 0.f;
        {
            const uint32_t kB = kB0 + cur * stB;
            #pragma unroll
            for (int ks = 0; ks < 4; ks++) {
                uint32_t bf[8][2];
                #pragma unroll
                for (int np = 0; np < 4; np++)
                    LDSM_X4(bf[np*2][0], bf[np*2][1], bf[np*2+1][0], bf[np*2+1][1],
                            kB + (uint32_t)((np * 16 * AST + ks * 16) * 2));
                #pragma unroll
                for (int nt = 0; nt < 8; nt++)
                    mma_h(s[nt], qf[ks], bf[nt]);
            }
        }

        // mask + exp -> PV A-fragments in registers + row-sum partials
        uint32_t pf[4][4];
        #pragma unroll
        for (int nt = 0; nt < 8; nt++) {
            int colj = k0t + nt * 8 + tg * 2;
            float p0 = (colj     > row0    ) ? 1.f : __expf(s[nt][0] * SCALE);
            float p1 = (colj + 1 > row0    ) ? 1.f : __expf(s[nt][1] * SCALE);
            float p2 = (colj     > row0 + 8) ? 1.f : __expf(s[nt][2] * SCALE);
            float p3 = (colj + 1 > row0 + 8) ? 1.f : __expf(s[nt][3] * SCALE);
            rs0 += p0 + p1;
            rs1 += p2 + p3;
            pf[nt >> 1][(nt & 1) * 2 + 0] = packh2(p0, p1);
            pf[nt >> 1][(nt & 1) * 2 + 1] = packh2(p2, p3);
        }

        // O += P @ V
        {
            const uint32_t vB = vB0 + cur * stB;
            #pragma unroll
            for (int kp2 = 0; kp2 < 4; kp2++) {
                uint32_t vf[8][2];
                #pragma unroll
                for (int np = 0; np < 4; np++)
                    LDSM_X4_T(vf[np*2][0], vf[np*2][1], vf[np*2+1][0], vf[np*2+1][1],
                              vB + (uint32_t)((kp2 * 16 * AST + np * 16) * 2));
                #pragma unroll
                for (int nt = 0; nt < 8; nt++)
                    mma_h(o[nt], pf[kp2], vf[nt]);
            }
        }
    }

    // add masked-tile contribution: P==1 -> suffix column sums of V
    #pragma unroll
    for (int nt = 0; nt < 8; nt++) {
        #pragma unroll
        for (int c2 = 0; c2 < 2; c2++) {
            float sv = suf[nt * 8 + tg * 2 + c2];
            o[nt][c2]     += sv;
            o[nt][2 + c2] += sv;
        }
    }

    // row sums: reduce over tg lanes, then add masked key count
    rs0 += __shfl_xor_sync(0xffffffffu, rs0, 1);
    rs0 += __shfl_xor_sync(0xffffffffu, rs0, 2);
    rs1 += __shfl_xor_sync(0xffffffffu, rs1, 1);
    rs1 += __shfl_xor_sync(0xffffffffu, rs1, 2);
    const float nmask = (float)(SEQ - ktEnd * 64);
    const float inv0 = 1.0f / (rs0 + nmask), inv1 = 1.0f / (rs1 + nmask);

    // normalize + scatter fp16 into scrambled layout:
    // [b,h,s,dh] -> ao[b][2c + (s>>10)][s & 1023], c = h*64+dh
    const int s0 = row0, s1 = row0 + 8;
    #pragma unroll
    for (int nt = 0; nt < 8; nt++) {
        #pragma unroll
        for (int c2 = 0; c2 < 2; c2++) {
            int dh = nt * 8 + tg * 2 + c2;
            int c  = h * 64 + dh;
            size_t rowb = (size_t)b * SEQ * DIM;
            ao[rowb + (size_t)(2*c + (s0 >> 10)) * DIM + (s0 & 1023)] =
                __float2half(o[nt][c2] * inv0);
            ao[rowb + (size_t)(2*c + (s1 >> 10)) * DIM + (s1 & 1023)] =
                __float2half(o[nt][2 + c2] * inv1);
        }
    }
}

// ---------------------------------------------------------------------------
extern "C" void kernel_launch(void* const* d_in, const int* in_sizes, int n_in,
                              void* d_out, int out_size)
{
    const float* x  = (const float*)d_in[0];
    const float* Wq = (const float*)d_in[2];
    const float* bq = (const float*)d_in[3];
    const float* Wk = (const float*)d_in[4];
    const float* bk = (const float*)d_in[5];
    const float* Wv = (const float*)d_in[6];
    const float* bv = (const float*)d_in[7];
    const float* Wo = (const float*)d_in[8];
    const float* bo = (const float*)d_in[9];
    float* out = (float*)d_out;

    __half *xh, *wh, *q, *k, *v, *aoh;
    float *ts;
    cudaGetSymbolAddress((void**)&xh,  g_xh);
    cudaGetSymbolAddress((void**)&wh,  g_wh);
    cudaGetSymbolAddress((void**)&q,   g_q);
    cudaGetSymbolAddress((void**)&k,   g_k);
    cudaGetSymbolAddress((void**)&v,   g_v);
    cudaGetSymbolAddress((void**)&aoh, g_aoh);
    cudaGetSymbolAddress((void**)&ts,  g_tsum);

    cudaFuncSetAttribute(gemm_h, cudaFuncAttributeMaxDynamicSharedMemorySize, GSMEM);
    cudaFuncSetAttribute(attn_h, cudaFuncAttributeMaxDynamicSharedMemorySize, ASMEM);

    convert_h<<<4096, 256>>>(x, Wq, Wk, Wv, Wo, xh, wh);

    dim3 gg(DIM / 256, MTOT / 128, 3);   // (4, 32, 3)
    gemm_h<<<gg, 256, GSMEM>>>(xh, wh, bq, bk, bv, q, k, v, nullptr, 0);

    dim3 gt(32, BATCH * HEADS);          // per-tile V column sums
    tilesum_k<<<gt, 64>>>(v, ts);

    dim3 ga(NQB, BATCH * HEADS);         // (16, 32)
    attn_h<<<ga, 256, ASMEM>>>(q, k, v, ts, aoh);

    dim3 go(DIM / 256, MTOT / 128, 1);
    gemm_h<<<go, 256, GSMEM>>>(aoh, wh + 3 * (size_t)DIM * DIM,
                               bo, bo, bo, q, q, q, out, 1);
}

// round 9
// speedup vs baseline: 12.3529x; 1.0636x over previous
#include <cuda_runtime.h>
#include <cuda_fp16.h>
#include <cstdint>

#define BATCH 2
#define HEADS 16
#define SEQ   2048
#define DIM   1024
#define HDIM  64
#define MTOT  (BATCH*SEQ)   // 4096
#define QSCALE 0.18033688011112043f   // HDIM^-0.5 * log2(e)
#define NQB   (SEQ/128)     // 16 query blocks per (b,h)

// Scratch (device globals: allocation-free rule)
__device__ __half g_xh[MTOT*DIM];              // x in fp16
__device__ __half g_wh[4*DIM*DIM];             // Wq|Wk|Wv|Wo in fp16
__device__ __half g_q[BATCH*HEADS*SEQ*HDIM];   // [b,h,s,dh], pre-scaled by QSCALE
__device__ __half g_k[BATCH*HEADS*SEQ*HDIM];
__device__ __half g_v[BATCH*HEADS*SEQ*HDIM];
__device__ __half g_aoh[MTOT*DIM];             // scrambled attn output (fp16)
__device__ float  g_tsum[BATCH*HEADS*32*HDIM]; // per-tile V column sums

// ---------------------------------------------------------------------------
// helpers
// ---------------------------------------------------------------------------
__device__ __forceinline__ uint32_t smem_u32(const void* p) {
    uint32_t a;
    asm("{ .reg .u64 t; cvta.to.shared.u64 t, %1; cvt.u32.u64 %0, t; }"
        : "=r"(a) : "l"(p));
    return a;
}
#define LDSM_X4(r0,r1,r2,r3,addr) \
    asm volatile("ldmatrix.sync.aligned.m8n8.x4.shared.b16 {%0,%1,%2,%3}, [%4];" \
        : "=r"(r0),"=r"(r1),"=r"(r2),"=r"(r3) : "r"(addr))
#define LDSM_X4_T(r0,r1,r2,r3,addr) \
    asm volatile("ldmatrix.sync.aligned.m8n8.x4.trans.shared.b16 {%0,%1,%2,%3}, [%4];" \
        : "=r"(r0),"=r"(r1),"=r"(r2),"=r"(r3) : "r"(addr))
#define CP16(smem, gptr) \
    asm volatile("cp.async.cg.shared.global [%0], [%1], 16;" :: "r"(smem), "l"(gptr))
#define CP_COMMIT() asm volatile("cp.async.commit_group;")
#define CP_WAIT(n)  asm volatile("cp.async.wait_group %0;" :: "n"(n))

__device__ __forceinline__ void mma_h(float c[4], const uint32_t a[4], const uint32_t b[2]) {
    asm volatile(
        "mma.sync.aligned.m16n8k16.row.col.f32.f16.f16.f32 "
        "{%0,%1,%2,%3}, {%4,%5,%6,%7}, {%8,%9}, {%0,%1,%2,%3};"
        : "+f"(c[0]), "+f"(c[1]), "+f"(c[2]), "+f"(c[3])
        : "r"(a[0]), "r"(a[1]), "r"(a[2]), "r"(a[3]), "r"(b[0]), "r"(b[1]));
}
__device__ __forceinline__ uint32_t packh2(float a, float b) {
    __half2 h = __floats2half2_rn(a, b);
    return *(uint32_t*)&h;
}

// ---------------------------------------------------------------------------
// one-shot f32 -> fp16 conversion of x and the four weight matrices
// ---------------------------------------------------------------------------
__global__ __launch_bounds__(256) void convert_h(
    const float* __restrict__ x,
    const float* __restrict__ wq, const float* __restrict__ wk,
    const float* __restrict__ wv, const float* __restrict__ wo,
    __half* __restrict__ xh, __half* __restrict__ wh)
{
    size_t t = (size_t)blockIdx.x * 256 + threadIdx.x;
    size_t base = t * 8;
    unsigned seg = (unsigned)(base >> 20);
    const float* src;
    __half* dst;
    if (seg < 4) { src = x + base; dst = xh + base; }
    else {
        size_t off = base - ((size_t)seg << 20);
        const float* w = (seg == 4) ? wq : (seg == 5) ? wk : (seg == 6) ? wv : wo;
        src = w + off;
        dst = wh + (base - ((size_t)4 << 20));
    }
    float4 a = *(const float4*)src;
    float4 b = *(const float4*)(src + 4);
    __half2 h[4] = {__floats2half2_rn(a.x, a.y), __floats2half2_rn(a.z, a.w),
                    __floats2half2_rn(b.x, b.y), __floats2half2_rn(b.z, b.w)};
    *(uint4*)dst = *(uint4*)h;
}

// ---------------------------------------------------------------------------
// per-tile V column sums: T[bh][kt][dh] = sum over the 64 keys of tile kt
// ---------------------------------------------------------------------------
__global__ __launch_bounds__(64) void tilesum_k(
    const __half* __restrict__ v, float* __restrict__ T)
{
    const int kt = blockIdx.x, bh = blockIdx.y, dh = threadIdx.x;
    const __half* vp = v + ((size_t)bh * SEQ + kt * 64) * HDIM + dh;
    float acc = 0.f;
    #pragma unroll
    for (int j = 0; j < 64; j++) acc += __half2float(vp[(size_t)j * HDIM]);
    T[((size_t)bh * 32 + kt) * HDIM + dh] = acc;
}

// ---------------------------------------------------------------------------
// fp16 GEMM (cp.async 3-stage): C = A(fp16) @ W^T(fp16) + bias
// CTA tile 128x256, BK=64, 256 threads, 8 warps 2x4 (warp tile 64x64)
// mode 0: scatter fp16 into [b,h,s,dh] (z==0 output scaled by QSCALE);
// mode 1: f32 row-major.
// ---------------------------------------------------------------------------
#define BK     64
#define GST    72
#define GASTG  (128*GST)
#define GBSTG  (256*GST)
#define GSMEM  ((3*(GASTG+GBSTG))*2)

__global__ __launch_bounds__(256) void gemm_h(
    const __half* __restrict__ A, const __half* __restrict__ Wb,
    const float* __restrict__ B0, const float* __restrict__ B1, const float* __restrict__ B2,
    __half* __restrict__ H0, __half* __restrict__ H1, __half* __restrict__ H2,
    float* __restrict__ Cf, int mode)
{
    extern __shared__ __half smg[];
    __half* As = smg;
    __half* Ws = smg + 3 * GASTG;

    const int z = blockIdx.z;
    const __half* W = Wb + (size_t)z * (DIM * DIM);
    const float* Bi = (z == 0) ? B0 : ((z == 1) ? B1 : B2);
    __half* Ho      = (z == 0) ? H0 : ((z == 1) ? H1 : H2);
    const float osc = (mode == 0 && z == 0) ? QSCALE : 1.0f;

    const int tid = threadIdx.x, lane = tid & 31, wid = tid >> 5;
    const int g = lane >> 2, tg = lane & 3;
    const int m0 = blockIdx.y * 128, n0 = blockIdx.x * 256;
    const int wm0 = (wid >> 2) * 64, wn0 = (wid & 3) * 64;

    float acc[4][8][4];
    #pragma unroll
    for (int mt = 0; mt < 4; mt++)
        #pragma unroll
        for (int nt = 0; nt < 8; nt++)
            #pragma unroll
            for (int r = 0; r < 4; r++) acc[mt][nt][r] = 0.f;

    const uint32_t aBase = smem_u32(As), wBase = smem_u32(Ws);
    const int ldRow = tid >> 3, ldCc = (tid & 7) * 8;

    auto load_stage = [&](int st, int kb) {
        const __half* Ag = A + (size_t)m0 * DIM + kb * BK;
        const __half* Wg = W + (size_t)n0 * DIM + kb * BK;
        uint32_t sa = aBase + (uint32_t)(st * GASTG) * 2;
        uint32_t sw = wBase + (uint32_t)(st * GBSTG) * 2;
        #pragma unroll
        for (int i = 0; i < 4; i++) {
            int row = ldRow + i * 32;
            CP16(sa + (uint32_t)(row * GST + ldCc) * 2, Ag + (size_t)row * DIM + ldCc);
        }
        #pragma unroll
        for (int i = 0; i < 8; i++) {
            int row = ldRow + i * 32;
            CP16(sw + (uint32_t)(row * GST + ldCc) * 2, Wg + (size_t)row * DIM + ldCc);
        }
        CP_COMMIT();
    };

    const uint32_t aLane = (uint32_t)(((wm0 + (lane & 15)) * GST + (lane >> 4) * 8) * 2);
    const int bRow = (lane & 7) + ((lane & 16) ? 8 : 0);
    const int bColH = (lane & 8) ? 8 : 0;
    const uint32_t bLane = (uint32_t)(((wn0 + bRow) * GST + bColH) * 2);
    const uint32_t aStB = (uint32_t)GASTG * 2, bStB = (uint32_t)GBSTG * 2;

    load_stage(0, 0);
    load_stage(1, 1);

    const int NKB = DIM / BK;   // 16
    for (int kb = 0; kb < NKB; kb++) {
        const int cur = kb % 3;
        if (kb == NKB - 1) { CP_WAIT(0); } else { CP_WAIT(1); }
        __syncthreads();
        if (kb + 2 < NKB) load_stage((kb + 2) % 3, kb + 2);

        const uint32_t aS = aBase + cur * aStB + aLane;
        const uint32_t bS = wBase + cur * bStB + bLane;
        #pragma unroll
        for (int ks = 0; ks < 4; ks++) {
            uint32_t af[4][4], bf[8][2];
            #pragma unroll
            for (int mt = 0; mt < 4; mt++)
                LDSM_X4(af[mt][0], af[mt][1], af[mt][2], af[mt][3],
                        aS + (uint32_t)((mt * 16 * GST + ks * 16) * 2));
            #pragma unroll
            for (int np = 0; np < 4; np++)
                LDSM_X4(bf[np*2][0], bf[np*2][1], bf[np*2+1][0], bf[np*2+1][1],
                        bS + (uint32_t)((np * 16 * GST + ks * 16) * 2));
            #pragma unroll
            for (int mt = 0; mt < 4; mt++)
                #pragma unroll
                for (int nt = 0; nt < 8; nt++)
                    mma_h(acc[mt][nt], af[mt], bf[nt]);
        }
        __syncthreads();
    }

    #pragma unroll
    for (int mt = 0; mt < 4; mt++) {
        #pragma unroll
        for (int nt = 0; nt < 8; nt++) {
            int col = n0 + wn0 + nt * 8 + tg * 2;
            float b0v = Bi[col], b1v = Bi[col + 1];
            #pragma unroll
            for (int h2 = 0; h2 < 2; h2++) {
                int row = m0 + wm0 + mt * 16 + g + h2 * 8;
                float v0 = (acc[mt][nt][h2*2 + 0] + b0v) * osc;
                float v1 = (acc[mt][nt][h2*2 + 1] + b1v) * osc;
                if (mode == 0) {
                    int b = row >> 11, s = row & 2047;
                    int hh = col >> 6, dh = col & 63;
                    size_t idx = (((size_t)(b * HEADS + hh)) * SEQ + s) * HDIM + dh;
                    *(__half2*)(Ho + idx) = __floats2half2_rn(v0, v1);
                } else {
                    *(float2*)(Cf + (size_t)row * DIM + col) = make_float2(v0, v1);
                }
            }
        }
    }
}

// ---------------------------------------------------------------------------
// fp16 attention with causal tile skipping + fp16x2 ex2 softmax + mma rowsums.
// Q pre-scaled by QSCALE -> QK^T accumulator IS the base-2 exponent argument.
// Dense softmax (mask=-1e-9 => P==1.0 exactly on masked entries).
// CTA: 128 queries x one (b,h), 256 threads; warp = 16 rows x full 64x64 tile.
// smem halves: Q[128][72] | K[2][64][72] | V[2][64][72] | suf (64 floats)
// ---------------------------------------------------------------------------
#define AST     72
#define AQ_OFF  0
#define AK_OFF  (128*AST)
#define AV_OFF  (AK_OFF + 2*64*AST)
#define AH_TOT  (AV_OFF + 2*64*AST)
#define ASMEM   (AH_TOT*2 + 64*4)

__global__ __launch_bounds__(256, 2) void attn_h(
    const __half* __restrict__ q, const __half* __restrict__ k,
    const __half* __restrict__ v, const float* __restrict__ Tsum,
    __half* __restrict__ ao)
{
    extern __shared__ __half sma[];
    float* suf = (float*)(sma + AH_TOT);

    const int tid = threadIdx.x, lane = tid & 31, wid = tid >> 5;
    const int g = lane >> 2, tg = lane & 3;
    const int bh = blockIdx.y, b = bh >> 4, h = bh & 15;
    const int iq = (NQB - 1) - blockIdx.x;      // heavy blocks scheduled first
    const int q0 = iq * 128;
    const int ktEnd = 2 * iq + 2;               // tiles to compute (>=2)

    const __half* qp = q + (size_t)bh * SEQ * HDIM;
    const __half* kp = k + (size_t)bh * SEQ * HDIM;
    const __half* vp = v + (size_t)bh * SEQ * HDIM;

    const uint32_t sBase = smem_u32(sma);

    const int kvRow = tid >> 3, kvCc = (tid & 7) * 8;
    auto load_kv = [&](int st, int kt) {
        const __half* Kg = kp + (size_t)(kt * 64) * HDIM;
        const __half* Vg = vp + (size_t)(kt * 64) * HDIM;
        uint32_t sk = sBase + (uint32_t)(AK_OFF + st * 64 * AST) * 2;
        uint32_t sv = sBase + (uint32_t)(AV_OFF + st * 64 * AST) * 2;
        #pragma unroll
        for (int i = 0; i < 2; i++) {
            int row = kvRow + i * 32;
            uint32_t so = (uint32_t)(row * AST + kvCc) * 2;
            CP16(sk + so, Kg + (size_t)row * HDIM + kvCc);
            CP16(sv + so, Vg + (size_t)row * HDIM + kvCc);
        }
        CP_COMMIT();
    };

    // prologue: Q tile + K/V stage 0
    {
        const int row = tid >> 1, cc = (tid & 1) * 32;
        #pragma unroll
        for (int i = 0; i < 4; i++)
            CP16(sBase + (uint32_t)(AQ_OFF + row * AST + cc + i * 8) * 2,
                 qp + (size_t)(q0 + row) * HDIM + cc + i * 8);
        uint32_t sk = sBase + (uint32_t)AK_OFF * 2;
        uint32_t sv = sBase + (uint32_t)AV_OFF * 2;
        #pragma unroll
        for (int i = 0; i < 2; i++) {
            int rowk = kvRow + i * 32;
            uint32_t so = (uint32_t)(rowk * AST + kvCc) * 2;
            CP16(sk + so, kp + (size_t)rowk * HDIM + kvCc);
            CP16(sv + so, vp + (size_t)rowk * HDIM + kvCc);
        }
        CP_COMMIT();
    }

    // V column suffix sum over masked tiles (overlaps cp.async)
    if (tid < 64) {
        float acc = 0.f;
        const float* tp = Tsum + ((size_t)bh * 32) * HDIM + tid;
        for (int kt = ktEnd; kt < 32; kt++) acc += tp[(size_t)kt * HDIM];
        suf[tid] = acc;
    }

    CP_WAIT(0);
    __syncthreads();

    // persistent Q fragments
    uint32_t qf[4][4];
    {
        const uint32_t qA = sBase +
            (uint32_t)((AQ_OFF + (wid * 16 + (lane & 15)) * AST + (lane >> 4) * 8) * 2);
        #pragma unroll
        for (int ks = 0; ks < 4; ks++)
            LDSM_X4(qf[ks][0], qf[ks][1], qf[ks][2], qf[ks][3], qA + (uint32_t)(ks * 32));
    }

    load_kv(1, 1);

    float o[8][4];
    float rsacc[4] = {0.f, 0.f, 0.f, 0.f};       // row sums via ones-B mma
    const uint32_t onesb[2] = {0x3C003C00u, 0x3C003C00u};
    #pragma unroll
    for (int nt = 0; nt < 8; nt++)
        #pragma unroll
        for (int r = 0; r < 4; r++) o[nt][r] = 0.f;

    const int bRow = (lane & 7) + ((lane & 16) ? 8 : 0);
    const int bColH = (lane & 8) ? 8 : 0;
    const int vRow = (lane & 7) + ((lane & 8) ? 8 : 0);
    const int vColH = (lane & 16) ? 8 : 0;
    const uint32_t stB = (uint32_t)(64 * AST * 2);
    const uint32_t kB0 = sBase + (uint32_t)((AK_OFF + bRow * AST + bColH) * 2);
    const uint32_t vB0 = sBase + (uint32_t)((AV_OFF + vRow * AST + vColH) * 2);
    const int row0 = q0 + wid * 16 + g;

    for (int kt = 0; kt < ktEnd; kt++) {
        const int cur = kt & 1;
        const int k0t = kt * 64;
        if (kt > 0) {
            CP_WAIT(0);
            __syncthreads();
            if (kt + 1 < ktEnd) load_kv(cur ^ 1, kt + 1);
        }

        // S = Qs @ K^T (accumulator = log2-domain exponent argument)
        float s[8][4];
        #pragma unroll
        for (int nt = 0; nt < 8; nt++)
            #pragma unroll
            for (int r = 0; r < 4; r++) s[nt][r] = 0.f;
        {
            const uint32_t kB = kB0 + cur * stB;
            #pragma unroll
            for (int ks = 0; ks < 4; ks++) {
                uint32_t bf[8][2];
                #pragma unroll
                for (int np = 0; np < 4; np++)
                    LDSM_X4(bf[np*2][0], bf[np*2][1], bf[np*2+1][0], bf[np*2+1][1],
                            kB + (uint32_t)((np * 16 * AST + ks * 16) * 2));
                #pragma unroll
                for (int nt = 0; nt < 8; nt++)
                    mma_h(s[nt], qf[ks], bf[nt]);
            }
        }

        // softmax: pack pairs -> ex2.approx.f16x2 -> PV A-fragments directly.
        // Mask (x=0 -> P=1.0 exactly) only on the <=2 diagonal-touching tiles.
        const bool diag = (kt + 2 >= ktEnd);
        uint32_t pf[4][4];
        #pragma unroll
        for (int nt = 0; nt < 8; nt++) {
            float x0 = s[nt][0], x1 = s[nt][1], x2 = s[nt][2], x3 = s[nt][3];
            if (diag) {
                int colj = k0t + nt * 8 + tg * 2;
                x0 = (colj     > row0    ) ? 0.f : x0;
                x1 = (colj + 1 > row0    ) ? 0.f : x1;
                x2 = (colj     > row0 + 8) ? 0.f : x2;
                x3 = (colj + 1 > row0 + 8) ? 0.f : x3;
            }
            uint32_t h01 = packh2(x0, x1), h23 = packh2(x2, x3);
            uint32_t p01, p23;
            asm("ex2.approx.f16x2 %0, %1;" : "=r"(p01) : "r"(h01));
            asm("ex2.approx.f16x2 %0, %1;" : "=r"(p23) : "r"(h23));
            pf[nt >> 1][(nt & 1) * 2 + 0] = p01;
            pf[nt >> 1][(nt & 1) * 2 + 1] = p23;
        }

        // O += P @ V, and row sums += P @ ones
        {
            const uint32_t vB = vB0 + cur * stB;
            #pragma unroll
            for (int kp2 = 0; kp2 < 4; kp2++) {
                uint32_t vf[8][2];
                #pragma unroll
                for (int np = 0; np < 4; np++)
                    LDSM_X4_T(vf[np*2][0], vf[np*2][1], vf[np*2+1][0], vf[np*2+1][1],
                              vB + (uint32_t)((kp2 * 16 * AST + np * 16) * 2));
                #pragma unroll
                for (int nt = 0; nt < 8; nt++)
                    mma_h(o[nt], pf[kp2], vf[nt]);
                mma_h(rsacc, pf[kp2], onesb);
            }
        }
    }

    // add masked-tile contribution: P==1 -> suffix column sums of V
    #pragma unroll
    for (int nt = 0; nt < 8; nt++) {
        #pragma unroll
        for (int c2 = 0; c2 < 2; c2++) {
            float sv = suf[nt * 8 + tg * 2 + c2];
            o[nt][c2]     += sv;
            o[nt][2 + c2] += sv;
        }
    }

    // row sums from ones-mma accumulator + masked key count
    const float nmask = (float)(SEQ - ktEnd * 64);
    const float inv0 = 1.0f / (rsacc[0] + nmask), inv1 = 1.0f / (rsacc[2] + nmask);

    // normalize + scatter fp16 into scrambled layout:
    // [b,h,s,dh] -> ao[b][2c + (s>>10)][s & 1023], c = h*64+dh
    const int s0 = row0, s1 = row0 + 8;
    #pragma unroll
    for (int nt = 0; nt < 8; nt++) {
        #pragma unroll
        for (int c2 = 0; c2 < 2; c2++) {
            int dh = nt * 8 + tg * 2 + c2;
            int c  = h * 64 + dh;
            size_t rowb = (size_t)b * SEQ * DIM;
            ao[rowb + (size_t)(2*c + (s0 >> 10)) * DIM + (s0 & 1023)] =
                __float2half(o[nt][c2] * inv0);
            ao[rowb + (size_t)(2*c + (s1 >> 10)) * DIM + (s1 & 1023)] =
                __float2half(o[nt][2 + c2] * inv1);
        }
    }
}

// ---------------------------------------------------------------------------
extern "C" void kernel_launch(void* const* d_in, const int* in_sizes, int n_in,
                              void* d_out, int out_size)
{
    const float* x  = (const float*)d_in[0];
    const float* Wq = (const float*)d_in[2];
    const float* bq = (const float*)d_in[3];
    const float* Wk = (const float*)d_in[4];
    const float* bk = (const float*)d_in[5];
    const float* Wv = (const float*)d_in[6];
    const float* bv = (const float*)d_in[7];
    const float* Wo = (const float*)d_in[8];
    const float* bo = (const float*)d_in[9];
    float* out = (float*)d_out;

    __half *xh, *wh, *q, *k, *v, *aoh;
    float *ts;
    cudaGetSymbolAddress((void**)&xh,  g_xh);
    cudaGetSymbolAddress((void**)&wh,  g_wh);
    cudaGetSymbolAddress((void**)&q,   g_q);
    cudaGetSymbolAddress((void**)&k,   g_k);
    cudaGetSymbolAddress((void**)&v,   g_v);
    cudaGetSymbolAddress((void**)&aoh, g_aoh);
    cudaGetSymbolAddress((void**)&ts,  g_tsum);

    cudaFuncSetAttribute(gemm_h, cudaFuncAttributeMaxDynamicSharedMemorySize, GSMEM);
    cudaFuncSetAttribute(attn_h, cudaFuncAttributeMaxDynamicSharedMemorySize, ASMEM);

    convert_h<<<4096, 256>>>(x, Wq, Wk, Wv, Wo, xh, wh);

    dim3 gg(DIM / 256, MTOT / 128, 3);   // (4, 32, 3)
    gemm_h<<<gg, 256, GSMEM>>>(xh, wh, bq, bk, bv, q, k, v, nullptr, 0);

    dim3 gt(32, BATCH * HEADS);          // per-tile V column sums
    tilesum_k<<<gt, 64>>>(v, ts);

    dim3 ga(NQB, BATCH * HEADS);         // (16, 32)
    attn_h<<<ga, 256, ASMEM>>>(q, k, v, ts, aoh);

    dim3 go(DIM / 256, MTOT / 128, 1);
    gemm_h<<<go, 256, GSMEM>>>(aoh, wh + 3 * (size_t)DIM * DIM,
                               bo, bo, bo, q, q, q, out, 1);
}

// round 10
// speedup vs baseline: 13.6623x; 1.1060x over previous
#include <cuda_runtime.h>
#include <cuda_fp16.h>
#include <cstdint>

#define BATCH 2
#define HEADS 16
#define SEQ   2048
#define DIM   1024
#define HDIM  64
#define MTOT  (BATCH*SEQ)   // 4096
#define QSCALE 0.18033688011112043f   // HDIM^-0.5 * log2(e)
#define NQB   (SEQ/128)     // 16 query blocks per (b,h)

// Scratch (device globals: allocation-free rule)
__device__ __half g_xh[MTOT*DIM];              // x in fp16
__device__ __half g_wh[4*DIM*DIM];             // Wq|Wk|Wv|Wo in fp16
__device__ __half g_q[BATCH*HEADS*SEQ*HDIM];   // [b,h,s,dh], pre-scaled by QSCALE
__device__ __half g_k[BATCH*HEADS*SEQ*HDIM];
__device__ __half g_v[BATCH*HEADS*SEQ*HDIM];
__device__ __half g_aoh[MTOT*DIM];             // scrambled attn output (fp16)
__device__ float  g_tsum[BATCH*HEADS*32*HDIM]; // per-tile V column sums

// ---------------------------------------------------------------------------
// helpers
// ---------------------------------------------------------------------------
__device__ __forceinline__ uint32_t smem_u32(const void* p) {
    uint32_t a;
    asm("{ .reg .u64 t; cvta.to.shared.u64 t, %1; cvt.u32.u64 %0, t; }"
        : "=r"(a) : "l"(p));
    return a;
}
#define LDSM_X4(r0,r1,r2,r3,addr) \
    asm volatile("ldmatrix.sync.aligned.m8n8.x4.shared.b16 {%0,%1,%2,%3}, [%4];" \
        : "=r"(r0),"=r"(r1),"=r"(r2),"=r"(r3) : "r"(addr))
#define LDSM_X4_T(r0,r1,r2,r3,addr) \
    asm volatile("ldmatrix.sync.aligned.m8n8.x4.trans.shared.b16 {%0,%1,%2,%3}, [%4];" \
        : "=r"(r0),"=r"(r1),"=r"(r2),"=r"(r3) : "r"(addr))
#define CP16(smem, gptr) \
    asm volatile("cp.async.cg.shared.global [%0], [%1], 16;" :: "r"(smem), "l"(gptr))
#define CP_COMMIT() asm volatile("cp.async.commit_group;")
#define CP_WAIT(n)  asm volatile("cp.async.wait_group %0;" :: "n"(n))

__device__ __forceinline__ void mma_h(float c[4], const uint32_t a[4], const uint32_t b[2]) {
    asm volatile(
        "mma.sync.aligned.m16n8k16.row.col.f32.f16.f16.f32 "
        "{%0,%1,%2,%3}, {%4,%5,%6,%7}, {%8,%9}, {%0,%1,%2,%3};"
        : "+f"(c[0]), "+f"(c[1]), "+f"(c[2]), "+f"(c[3])
        : "r"(a[0]), "r"(a[1]), "r"(a[2]), "r"(a[3]), "r"(b[0]), "r"(b[1]));
}
__device__ __forceinline__ uint32_t packh2(float a, float b) {
    __half2 h = __floats2half2_rn(a, b);
    return *(uint32_t*)&h;
}

// ---------------------------------------------------------------------------
// one-shot f32 -> fp16 conversion of x and the four weight matrices
// ---------------------------------------------------------------------------
__global__ __launch_bounds__(256) void convert_h(
    const float* __restrict__ x,
    const float* __restrict__ wq, const float* __restrict__ wk,
    const float* __restrict__ wv, const float* __restrict__ wo,
    __half* __restrict__ xh, __half* __restrict__ wh)
{
    size_t t = (size_t)blockIdx.x * 256 + threadIdx.x;
    size_t base = t * 8;
    unsigned seg = (unsigned)(base >> 20);
    const float* src;
    __half* dst;
    if (seg < 4) { src = x + base; dst = xh + base; }
    else {
        size_t off = base - ((size_t)seg << 20);
        const float* w = (seg == 4) ? wq : (seg == 5) ? wk : (seg == 6) ? wv : wo;
        src = w + off;
        dst = wh + (base - ((size_t)4 << 20));
    }
    float4 a = *(const float4*)src;
    float4 b = *(const float4*)(src + 4);
    __half2 h[4] = {__floats2half2_rn(a.x, a.y), __floats2half2_rn(a.z, a.w),
                    __floats2half2_rn(b.x, b.y), __floats2half2_rn(b.z, b.w)};
    *(uint4*)dst = *(uint4*)h;
}

// ---------------------------------------------------------------------------
// per-tile V column sums: T[bh][kt][dh] = sum over the 64 keys of tile kt
// ---------------------------------------------------------------------------
__global__ __launch_bounds__(64) void tilesum_k(
    const __half* __restrict__ v, float* __restrict__ T)
{
    const int kt = blockIdx.x, bh = blockIdx.y, dh = threadIdx.x;
    const __half* vp = v + ((size_t)bh * SEQ + kt * 64) * HDIM + dh;
    float acc = 0.f;
    #pragma unroll
    for (int j = 0; j < 64; j++) acc += __half2float(vp[(size_t)j * HDIM]);
    T[((size_t)bh * 32 + kt) * HDIM + dh] = acc;
}

// ---------------------------------------------------------------------------
// fp16 GEMM (cp.async 3-stage): C = A(fp16) @ W^T(fp16) + bias
// CTA tile 128x256, BK=64, 256 threads, 8 warps 2x4 (warp tile 64x64)
// mode 0: scatter fp16 into [b,h,s,dh] (z==0 output scaled by QSCALE);
// mode 1: f32 row-major.
// ---------------------------------------------------------------------------
#define BK     64
#define GST    72
#define GASTG  (128*GST)
#define GBSTG  (256*GST)
#define GSMEM  ((3*(GASTG+GBSTG))*2)

__global__ __launch_bounds__(256) void gemm_h(
    const __half* __restrict__ A, const __half* __restrict__ Wb,
    const float* __restrict__ B0, const float* __restrict__ B1, const float* __restrict__ B2,
    __half* __restrict__ H0, __half* __restrict__ H1, __half* __restrict__ H2,
    float* __restrict__ Cf, int mode)
{
    extern __shared__ __half smg[];
    __half* As = smg;
    __half* Ws = smg + 3 * GASTG;

    const int z = blockIdx.z;
    const __half* W = Wb + (size_t)z * (DIM * DIM);
    const float* Bi = (z == 0) ? B0 : ((z == 1) ? B1 : B2);
    __half* Ho      = (z == 0) ? H0 : ((z == 1) ? H1 : H2);
    const float osc = (mode == 0 && z == 0) ? QSCALE : 1.0f;

    const int tid = threadIdx.x, lane = tid & 31, wid = tid >> 5;
    const int g = lane >> 2, tg = lane & 3;
    const int m0 = blockIdx.y * 128, n0 = blockIdx.x * 256;
    const int wm0 = (wid >> 2) * 64, wn0 = (wid & 3) * 64;

    float acc[4][8][4];
    #pragma unroll
    for (int mt = 0; mt < 4; mt++)
        #pragma unroll
        for (int nt = 0; nt < 8; nt++)
            #pragma unroll
            for (int r = 0; r < 4; r++) acc[mt][nt][r] = 0.f;

    const uint32_t aBase = smem_u32(As), wBase = smem_u32(Ws);
    const int ldRow = tid >> 3, ldCc = (tid & 7) * 8;

    auto load_stage = [&](int st, int kb) {
        const __half* Ag = A + (size_t)m0 * DIM + kb * BK;
        const __half* Wg = W + (size_t)n0 * DIM + kb * BK;
        uint32_t sa = aBase + (uint32_t)(st * GASTG) * 2;
        uint32_t sw = wBase + (uint32_t)(st * GBSTG) * 2;
        #pragma unroll
        for (int i = 0; i < 4; i++) {
            int row = ldRow + i * 32;
            CP16(sa + (uint32_t)(row * GST + ldCc) * 2, Ag + (size_t)row * DIM + ldCc);
        }
        #pragma unroll
        for (int i = 0; i < 8; i++) {
            int row = ldRow + i * 32;
            CP16(sw + (uint32_t)(row * GST + ldCc) * 2, Wg + (size_t)row * DIM + ldCc);
        }
        CP_COMMIT();
    };

    const uint32_t aLane = (uint32_t)(((wm0 + (lane & 15)) * GST + (lane >> 4) * 8) * 2);
    const int bRow = (lane & 7) + ((lane & 16) ? 8 : 0);
    const int bColH = (lane & 8) ? 8 : 0;
    const uint32_t bLane = (uint32_t)(((wn0 + bRow) * GST + bColH) * 2);
    const uint32_t aStB = (uint32_t)GASTG * 2, bStB = (uint32_t)GBSTG * 2;

    load_stage(0, 0);
    load_stage(1, 1);

    const int NKB = DIM / BK;   // 16
    for (int kb = 0; kb < NKB; kb++) {
        const int cur = kb % 3;
        if (kb == NKB - 1) { CP_WAIT(0); } else { CP_WAIT(1); }
        __syncthreads();
        if (kb + 2 < NKB) load_stage((kb + 2) % 3, kb + 2);

        const uint32_t aS = aBase + cur * aStB + aLane;
        const uint32_t bS = wBase + cur * bStB + bLane;
        #pragma unroll
        for (int ks = 0; ks < 4; ks++) {
            uint32_t af[4][4], bf[8][2];
            #pragma unroll
            for (int mt = 0; mt < 4; mt++)
                LDSM_X4(af[mt][0], af[mt][1], af[mt][2], af[mt][3],
                        aS + (uint32_t)((mt * 16 * GST + ks * 16) * 2));
            #pragma unroll
            for (int np = 0; np < 4; np++)
                LDSM_X4(bf[np*2][0], bf[np*2][1], bf[np*2+1][0], bf[np*2+1][1],
                        bS + (uint32_t)((np * 16 * GST + ks * 16) * 2));
            #pragma unroll
            for (int mt = 0; mt < 4; mt++)
                #pragma unroll
                for (int nt = 0; nt < 8; nt++)
                    mma_h(acc[mt][nt], af[mt], bf[nt]);
        }
        __syncthreads();
    }

    #pragma unroll
    for (int mt = 0; mt < 4; mt++) {
        #pragma unroll
        for (int nt = 0; nt < 8; nt++) {
            int col = n0 + wn0 + nt * 8 + tg * 2;
            float b0v = Bi[col], b1v = Bi[col + 1];
            #pragma unroll
            for (int h2 = 0; h2 < 2; h2++) {
                int row = m0 + wm0 + mt * 16 + g + h2 * 8;
                float v0 = (acc[mt][nt][h2*2 + 0] + b0v) * osc;
                float v1 = (acc[mt][nt][h2*2 + 1] + b1v) * osc;
                if (mode == 0) {
                    int b = row >> 11, s = row & 2047;
                    int hh = col >> 6, dh = col & 63;
                    size_t idx = (((size_t)(b * HEADS + hh)) * SEQ + s) * HDIM + dh;
                    *(__half2*)(Ho + idx) = __floats2half2_rn(v0, v1);
                } else {
                    *(float2*)(Cf + (size_t)row * DIM + col) = make_float2(v0, v1);
                }
            }
        }
    }
}

// ---------------------------------------------------------------------------
// fp16 attention: causal tile skipping + ex2.f16x2 softmax + mma rowsums +
// LPT-balanced static schedule. 296 CTAs, each handles 1-2 (bh,iq) items:
//   rank r (weight-sorted desc): bh = r&31, iq = 15-(r>>5), weight 2iq+2.
//   CTA j<80: single item rank j. CTA j in [80,296): pair (j, 591-j).
// smem halves: Q[128][72] | K[2][64][72] | V[2][64][72] | suf (64 floats)
// ---------------------------------------------------------------------------
#define AST     72
#define AQ_OFF  0
#define AK_OFF  (128*AST)
#define AV_OFF  (AK_OFF + 2*64*AST)
#define AH_TOT  (AV_OFF + 2*64*AST)
#define ASMEM   (AH_TOT*2 + 64*4)
#define NCTA_A  296

__global__ __launch_bounds__(256, 2) void attn_h(
    const __half* __restrict__ q, const __half* __restrict__ k,
    const __half* __restrict__ v, const float* __restrict__ Tsum,
    __half* __restrict__ ao)
{
    extern __shared__ __half sma[];
    float* suf = (float*)(sma + AH_TOT);

    const int tid = threadIdx.x, lane = tid & 31, wid = tid >> 5;
    const int g = lane >> 2, tg = lane & 3;
    const int j = blockIdx.x;
    const int nitems = (j < 80) ? 1 : 2;

    const uint32_t sBase = smem_u32(sma);
    const int kvRow = tid >> 3, kvCc = (tid & 7) * 8;
    const int bRowL = (lane & 7) + ((lane & 16) ? 8 : 0);
    const int bColH = (lane & 8) ? 8 : 0;
    const int vRowL = (lane & 7) + ((lane & 8) ? 8 : 0);
    const int vColH = (lane & 16) ? 8 : 0;
    const uint32_t stB = (uint32_t)(64 * AST * 2);
    const uint32_t kB0 = sBase + (uint32_t)((AK_OFF + bRowL * AST + bColH) * 2);
    const uint32_t vB0 = sBase + (uint32_t)((AV_OFF + vRowL * AST + vColH) * 2);
    const uint32_t onesb[2] = {0x3C003C00u, 0x3C003C00u};

    for (int it = 0; it < nitems; it++) {
        const int r  = (it == 0) ? j : (591 - j);
        const int bh = r & 31;
        const int iq = 15 - (r >> 5);
        const int b  = bh >> 4, h = bh & 15;
        const int q0 = iq * 128;
        const int ktEnd = 2 * iq + 2;

        const __half* qp = q + (size_t)bh * SEQ * HDIM;
        const __half* kp = k + (size_t)bh * SEQ * HDIM;
        const __half* vp = v + (size_t)bh * SEQ * HDIM;

        if (it > 0) __syncthreads();   // protect smem reuse across items

        // prologue: Q tile + K/V stage 0
        {
            const int row = tid >> 1, cc = (tid & 1) * 32;
            #pragma unroll
            for (int i = 0; i < 4; i++)
                CP16(sBase + (uint32_t)(AQ_OFF + row * AST + cc + i * 8) * 2,
                     qp + (size_t)(q0 + row) * HDIM + cc + i * 8);
            uint32_t sk = sBase + (uint32_t)AK_OFF * 2;
            uint32_t sv = sBase + (uint32_t)AV_OFF * 2;
            #pragma unroll
            for (int i = 0; i < 2; i++) {
                int rowk = kvRow + i * 32;
                uint32_t so = (uint32_t)(rowk * AST + kvCc) * 2;
                CP16(sk + so, kp + (size_t)rowk * HDIM + kvCc);
                CP16(sv + so, vp + (size_t)rowk * HDIM + kvCc);
            }
            CP_COMMIT();
        }

        // V column suffix sum over masked tiles (overlaps cp.async)
        if (tid < 64) {
            float acc = 0.f;
            const float* tp = Tsum + ((size_t)bh * 32) * HDIM + tid;
            for (int kt = ktEnd; kt < 32; kt++) acc += tp[(size_t)kt * HDIM];
            suf[tid] = acc;
        }

        CP_WAIT(0);
        __syncthreads();

        // persistent Q fragments
        uint32_t qf[4][4];
        {
            const uint32_t qA = sBase +
                (uint32_t)((AQ_OFF + (wid * 16 + (lane & 15)) * AST + (lane >> 4) * 8) * 2);
            #pragma unroll
            for (int ks = 0; ks < 4; ks++)
                LDSM_X4(qf[ks][0], qf[ks][1], qf[ks][2], qf[ks][3], qA + (uint32_t)(ks * 32));
        }

        {
            const __half* Kg = kp + (size_t)64 * HDIM;
            const __half* Vg = vp + (size_t)64 * HDIM;
            uint32_t sk = sBase + (uint32_t)(AK_OFF + 64 * AST) * 2;
            uint32_t sv = sBase + (uint32_t)(AV_OFF + 64 * AST) * 2;
            #pragma unroll
            for (int i = 0; i < 2; i++) {
                int row = kvRow + i * 32;
                uint32_t so = (uint32_t)(row * AST + kvCc) * 2;
                CP16(sk + so, Kg + (size_t)row * HDIM + kvCc);
                CP16(sv + so, Vg + (size_t)row * HDIM + kvCc);
            }
            CP_COMMIT();
        }

        float o[8][4];
        float rsacc[4] = {0.f, 0.f, 0.f, 0.f};
        #pragma unroll
        for (int nt = 0; nt < 8; nt++)
            #pragma unroll
            for (int rr = 0; rr < 4; rr++) o[nt][rr] = 0.f;

        const int row0 = q0 + wid * 16 + g;

        for (int kt = 0; kt < ktEnd; kt++) {
            const int cur = kt & 1;
            const int k0t = kt * 64;
            if (kt > 0) {
                CP_WAIT(0);
                __syncthreads();
                if (kt + 1 < ktEnd) {
                    const int st = cur ^ 1, ktn = kt + 1;
                    const __half* Kg = kp + (size_t)(ktn * 64) * HDIM;
                    const __half* Vg = vp + (size_t)(ktn * 64) * HDIM;
                    uint32_t sk = sBase + (uint32_t)(AK_OFF + st * 64 * AST) * 2;
                    uint32_t sv = sBase + (uint32_t)(AV_OFF + st * 64 * AST) * 2;
                    #pragma unroll
                    for (int i = 0; i < 2; i++) {
                        int row = kvRow + i * 32;
                        uint32_t so = (uint32_t)(row * AST + kvCc) * 2;
                        CP16(sk + so, Kg + (size_t)row * HDIM + kvCc);
                        CP16(sv + so, Vg + (size_t)row * HDIM + kvCc);
                    }
                    CP_COMMIT();
                }
            }

            // S = Qs @ K^T (accumulator = base-2 exponent argument)
            float s[8][4];
            #pragma unroll
            for (int nt = 0; nt < 8; nt++)
                #pragma unroll
                for (int rr = 0; rr < 4; rr++) s[nt][rr] = 0.f;
            {
                const uint32_t kB = kB0 + cur * stB;
                #pragma unroll
                for (int ks = 0; ks < 4; ks++) {
                    uint32_t bf[8][2];
                    #pragma unroll
                    for (int np = 0; np < 4; np++)
                        LDSM_X4(bf[np*2][0], bf[np*2][1], bf[np*2+1][0], bf[np*2+1][1],
                                kB + (uint32_t)((np * 16 * AST + ks * 16) * 2));
                    #pragma unroll
                    for (int nt = 0; nt < 8; nt++)
                        mma_h(s[nt], qf[ks], bf[nt]);
                }
            }

            // softmax: pack -> ex2.approx.f16x2 -> PV A-fragments.
            // mask (x=0 -> P=1.0) only on diagonal-touching tiles.
            const bool diag = (kt + 2 >= ktEnd);
            uint32_t pf[4][4];
            #pragma unroll
            for (int nt = 0; nt < 8; nt++) {
                float x0 = s[nt][0], x1 = s[nt][1], x2 = s[nt][2], x3 = s[nt][3];
                if (diag) {
                    int colj = k0t + nt * 8 + tg * 2;
                    x0 = (colj     > row0    ) ? 0.f : x0;
                    x1 = (colj + 1 > row0    ) ? 0.f : x1;
                    x2 = (colj     > row0 + 8) ? 0.f : x2;
                    x3 = (colj + 1 > row0 + 8) ? 0.f : x3;
                }
                uint32_t h01 = packh2(x0, x1), h23 = packh2(x2, x3);
                uint32_t p01, p23;
                asm("ex2.approx.f16x2 %0, %1;" : "=r"(p01) : "r"(h01));
                asm("ex2.approx.f16x2 %0, %1;" : "=r"(p23) : "r"(h23));
                pf[nt >> 1][(nt & 1) * 2 + 0] = p01;
                pf[nt >> 1][(nt & 1) * 2 + 1] = p23;
            }

            // O += P @ V, row sums += P @ ones
            {
                const uint32_t vB = vB0 + cur * stB;
                #pragma unroll
                for (int kp2 = 0; kp2 < 4; kp2++) {
                    uint32_t vf[8][2];
                    #pragma unroll
                    for (int np = 0; np < 4; np++)
                        LDSM_X4_T(vf[np*2][0], vf[np*2][1], vf[np*2+1][0], vf[np*2+1][1],
                                  vB + (uint32_t)((kp2 * 16 * AST + np * 16) * 2));
                    #pragma unroll
                    for (int nt = 0; nt < 8; nt++)
                        mma_h(o[nt], pf[kp2], vf[nt]);
                    mma_h(rsacc, pf[kp2], onesb);
                }
            }
        }

        // masked-tile contribution (P==1): suffix column sums of V
        #pragma unroll
        for (int nt = 0; nt < 8; nt++) {
            #pragma unroll
            for (int c2 = 0; c2 < 2; c2++) {
                float sv = suf[nt * 8 + tg * 2 + c2];
                o[nt][c2]     += sv;
                o[nt][2 + c2] += sv;
            }
        }

        const float nmask = (float)(SEQ - ktEnd * 64);
        const float inv0 = 1.0f / (rsacc[0] + nmask), inv1 = 1.0f / (rsacc[2] + nmask);

        // normalize + scatter fp16 into scrambled layout:
        // [b,h,s,dh] -> ao[b][2c + (s>>10)][s & 1023], c = h*64+dh
        const int s0 = row0, s1 = row0 + 8;
        #pragma unroll
        for (int nt = 0; nt < 8; nt++) {
            #pragma unroll
            for (int c2 = 0; c2 < 2; c2++) {
                int dh = nt * 8 + tg * 2 + c2;
                int c  = h * 64 + dh;
                size_t rowb = (size_t)b * SEQ * DIM;
                ao[rowb + (size_t)(2*c + (s0 >> 10)) * DIM + (s0 & 1023)] =
                    __float2half(o[nt][c2] * inv0);
                ao[rowb + (size_t)(2*c + (s1 >> 10)) * DIM + (s1 & 1023)] =
                    __float2half(o[nt][2 + c2] * inv1);
            }
        }
    }
}

// ---------------------------------------------------------------------------
extern "C" void kernel_launch(void* const* d_in, const int* in_sizes, int n_in,
                              void* d_out, int out_size)
{
    const float* x  = (const float*)d_in[0];
    const float* Wq = (const float*)d_in[2];
    const float* bq = (const float*)d_in[3];
    const float* Wk = (const float*)d_in[4];
    const float* bk = (const float*)d_in[5];
    const float* Wv = (const float*)d_in[6];
    const float* bv = (const float*)d_in[7];
    const float* Wo = (const float*)d_in[8];
    const float* bo = (const float*)d_in[9];
    float* out = (float*)d_out;

    __half *xh, *wh, *q, *k, *v, *aoh;
    float *ts;
    cudaGetSymbolAddress((void**)&xh,  g_xh);
    cudaGetSymbolAddress((void**)&wh,  g_wh);
    cudaGetSymbolAddress((void**)&q,   g_q);
    cudaGetSymbolAddress((void**)&k,   g_k);
    cudaGetSymbolAddress((void**)&v,   g_v);
    cudaGetSymbolAddress((void**)&aoh, g_aoh);
    cudaGetSymbolAddress((void**)&ts,  g_tsum);

    cudaFuncSetAttribute(gemm_h, cudaFuncAttributeMaxDynamicSharedMemorySize, GSMEM);
    cudaFuncSetAttribute(attn_h, cudaFuncAttributeMaxDynamicSharedMemorySize, ASMEM);

    convert_h<<<4096, 256>>>(x, Wq, Wk, Wv, Wo, xh, wh);

    dim3 gg(DIM / 256, MTOT / 128, 3);   // (4, 32, 3)
    gemm_h<<<gg, 256, GSMEM>>>(xh, wh, bq, bk, bv, q, k, v, nullptr, 0);

    dim3 gt(32, BATCH * HEADS);          // per-tile V column sums
    tilesum_k<<<gt, 64>>>(v, ts);

    attn_h<<<NCTA_A, 256, ASMEM>>>(q, k, v, ts, aoh);

    dim3 go(DIM / 256, MTOT / 128, 1);
    gemm_h<<<go, 256, GSMEM>>>(aoh, wh + 3 * (size_t)DIM * DIM,
                               bo, bo, bo, q, q, q, out, 1);
}

// round 11
// speedup vs baseline: 13.7764x; 1.0084x over previous
#include <cuda_runtime.h>
#include <cuda_fp16.h>
#include <cstdint>

#define BATCH 2
#define HEADS 16
#define SEQ   2048
#define DIM   1024
#define HDIM  64
#define MTOT  (BATCH*SEQ)   // 4096
#define QSCALE 0.18033688011112043f   // HDIM^-0.5 * log2(e)
#define NQB   (SEQ/128)     // 16 query blocks per (b,h)

// Scratch (device globals: allocation-free rule)
__device__ __half g_xh[MTOT*DIM];              // x in fp16
__device__ __half g_wh[4*DIM*DIM];             // Wq|Wk|Wv|Wo in fp16
__device__ __half g_q[BATCH*HEADS*SEQ*HDIM];   // [b,h,s,dh], pre-scaled by QSCALE
__device__ __half g_k[BATCH*HEADS*SEQ*HDIM];
__device__ __half g_v[BATCH*HEADS*SEQ*HDIM];
__device__ __half g_aoh[MTOT*DIM];             // scrambled attn output (fp16)
__device__ float  g_tsum[BATCH*HEADS*32*HDIM]; // per-tile V column sums

// ---------------------------------------------------------------------------
// helpers
// ---------------------------------------------------------------------------
__device__ __forceinline__ uint32_t smem_u32(const void* p) {
    uint32_t a;
    asm("{ .reg .u64 t; cvta.to.shared.u64 t, %1; cvt.u32.u64 %0, t; }"
        : "=r"(a) : "l"(p));
    return a;
}
#define LDSM_X4(r0,r1,r2,r3,addr) \
    asm volatile("ldmatrix.sync.aligned.m8n8.x4.shared.b16 {%0,%1,%2,%3}, [%4];" \
        : "=r"(r0),"=r"(r1),"=r"(r2),"=r"(r3) : "r"(addr))
#define LDSM_X4_T(r0,r1,r2,r3,addr) \
    asm volatile("ldmatrix.sync.aligned.m8n8.x4.trans.shared.b16 {%0,%1,%2,%3}, [%4];" \
        : "=r"(r0),"=r"(r1),"=r"(r2),"=r"(r3) : "r"(addr))
#define CP16(smem, gptr) \
    asm volatile("cp.async.cg.shared.global [%0], [%1], 16;" :: "r"(smem), "l"(gptr))
#define CP_COMMIT() asm volatile("cp.async.commit_group;")
#define CP_WAIT(n)  asm volatile("cp.async.wait_group %0;" :: "n"(n))

__device__ __forceinline__ void mma_h(float c[4], const uint32_t a[4], const uint32_t b[2]) {
    asm volatile(
        "mma.sync.aligned.m16n8k16.row.col.f32.f16.f16.f32 "
        "{%0,%1,%2,%3}, {%4,%5,%6,%7}, {%8,%9}, {%0,%1,%2,%3};"
        : "+f"(c[0]), "+f"(c[1]), "+f"(c[2]), "+f"(c[3])
        : "r"(a[0]), "r"(a[1]), "r"(a[2]), "r"(a[3]), "r"(b[0]), "r"(b[1]));
}
__device__ __forceinline__ uint32_t packh2(float a, float b) {
    __half2 h = __floats2half2_rn(a, b);
    return *(uint32_t*)&h;
}

// ---------------------------------------------------------------------------
// one-shot f32 -> fp16 conversion of x and the four weight matrices
// ---------------------------------------------------------------------------
__global__ __launch_bounds__(256) void convert_h(
    const float* __restrict__ x,
    const float* __restrict__ wq, const float* __restrict__ wk,
    const float* __restrict__ wv, const float* __restrict__ wo,
    __half* __restrict__ xh, __half* __restrict__ wh)
{
    size_t t = (size_t)blockIdx.x * 256 + threadIdx.x;
    size_t base = t * 8;
    unsigned seg = (unsigned)(base >> 20);
    const float* src;
    __half* dst;
    if (seg < 4) { src = x + base; dst = xh + base; }
    else {
        size_t off = base - ((size_t)seg << 20);
        const float* w = (seg == 4) ? wq : (seg == 5) ? wk : (seg == 6) ? wv : wo;
        src = w + off;
        dst = wh + (base - ((size_t)4 << 20));
    }
    float4 a = *(const float4*)src;
    float4 b = *(const float4*)(src + 4);
    __half2 h[4] = {__floats2half2_rn(a.x, a.y), __floats2half2_rn(a.z, a.w),
                    __floats2half2_rn(b.x, b.y), __floats2half2_rn(b.z, b.w)};
    *(uint4*)dst = *(uint4*)h;
}

// ---------------------------------------------------------------------------
// per-tile V column sums: T[bh][kt][dh] = sum over the 64 keys of tile kt
// ---------------------------------------------------------------------------
__global__ __launch_bounds__(64) void tilesum_k(
    const __half* __restrict__ v, float* __restrict__ T)
{
    const int kt = blockIdx.x, bh = blockIdx.y, dh = threadIdx.x;
    const __half* vp = v + ((size_t)bh * SEQ + kt * 64) * HDIM + dh;
    float acc = 0.f;
    #pragma unroll
    for (int j = 0; j < 64; j++) acc += __half2float(vp[(size_t)j * HDIM]);
    T[((size_t)bh * 32 + kt) * HDIM + dh] = acc;
}

// ---------------------------------------------------------------------------
// fp16 GEMM (cp.async 3-stage): C = A(fp16) @ W^T(fp16) + bias
// CTA tile 128x128, BK=64, 256 threads, 8 warps 2x4 (warp tile 64x32)
// smem 108KB -> 2 CTAs/SM (the occupancy lever).
// mode 0: scatter fp16 into [b,h,s,dh] (z==0 output scaled by QSCALE);
// mode 1: f32 row-major.
// ---------------------------------------------------------------------------
#define BK     64
#define GST    72
#define GSTAGE (128*GST)            // halves per operand per stage
#define GSMEM  (6*GSTAGE*2)         // 3 stages x (A+W) = 110592 B

__global__ __launch_bounds__(256, 2) void gemm_h(
    const __half* __restrict__ A, const __half* __restrict__ Wb,
    const float* __restrict__ B0, const float* __restrict__ B1, const float* __restrict__ B2,
    __half* __restrict__ H0, __half* __restrict__ H1, __half* __restrict__ H2,
    float* __restrict__ Cf, int mode)
{
    extern __shared__ __half smg[];
    __half* As = smg;
    __half* Ws = smg + 3 * GSTAGE;

    const int z = blockIdx.z;
    const __half* W = Wb + (size_t)z * (DIM * DIM);
    const float* Bi = (z == 0) ? B0 : ((z == 1) ? B1 : B2);
    __half* Ho      = (z == 0) ? H0 : ((z == 1) ? H1 : H2);
    const float osc = (mode == 0 && z == 0) ? QSCALE : 1.0f;

    const int tid = threadIdx.x, lane = tid & 31, wid = tid >> 5;
    const int g = lane >> 2, tg = lane & 3;
    const int m0 = blockIdx.y * 128, n0 = blockIdx.x * 128;
    const int wm0 = (wid >> 2) * 64, wn0 = (wid & 3) * 32;

    float acc[4][4][4];
    #pragma unroll
    for (int mt = 0; mt < 4; mt++)
        #pragma unroll
        for (int nt = 0; nt < 4; nt++)
            #pragma unroll
            for (int r = 0; r < 4; r++) acc[mt][nt][r] = 0.f;

    const uint32_t aBase = smem_u32(As), wBase = smem_u32(Ws);
    const int ldRow = tid >> 3, ldCc = (tid & 7) * 8;

    auto load_stage = [&](int st, int kb) {
        const __half* Ag = A + (size_t)m0 * DIM + kb * BK;
        const __half* Wg = W + (size_t)n0 * DIM + kb * BK;
        uint32_t sa = aBase + (uint32_t)(st * GSTAGE) * 2;
        uint32_t sw = wBase + (uint32_t)(st * GSTAGE) * 2;
        #pragma unroll
        for (int i = 0; i < 4; i++) {
            int row = ldRow + i * 32;
            uint32_t so = (uint32_t)(row * GST + ldCc) * 2;
            CP16(sa + so, Ag + (size_t)row * DIM + ldCc);
            CP16(sw + so, Wg + (size_t)row * DIM + ldCc);
        }
        CP_COMMIT();
    };

    const uint32_t aLane = (uint32_t)(((wm0 + (lane & 15)) * GST + (lane >> 4) * 8) * 2);
    const int bRow = (lane & 7) + ((lane & 16) ? 8 : 0);
    const int bColH = (lane & 8) ? 8 : 0;
    const uint32_t bLane = (uint32_t)(((wn0 + bRow) * GST + bColH) * 2);
    const uint32_t stageB = (uint32_t)GSTAGE * 2;

    load_stage(0, 0);
    load_stage(1, 1);

    const int NKB = DIM / BK;   // 16
    for (int kb = 0; kb < NKB; kb++) {
        const int cur = kb % 3;
        if (kb == NKB - 1) { CP_WAIT(0); } else { CP_WAIT(1); }
        __syncthreads();
        if (kb + 2 < NKB) load_stage((kb + 2) % 3, kb + 2);

        const uint32_t aS = aBase + cur * stageB + aLane;
        const uint32_t bS = wBase + cur * stageB + bLane;
        #pragma unroll
        for (int ks = 0; ks < 4; ks++) {
            uint32_t af[4][4], bf[4][2];
            #pragma unroll
            for (int mt = 0; mt < 4; mt++)
                LDSM_X4(af[mt][0], af[mt][1], af[mt][2], af[mt][3],
                        aS + (uint32_t)((mt * 16 * GST + ks * 16) * 2));
            #pragma unroll
            for (int np = 0; np < 2; np++)
                LDSM_X4(bf[np*2][0], bf[np*2][1], bf[np*2+1][0], bf[np*2+1][1],
                        bS + (uint32_t)((np * 16 * GST + ks * 16) * 2));
            #pragma unroll
            for (int mt = 0; mt < 4; mt++)
                #pragma unroll
                for (int nt = 0; nt < 4; nt++)
                    mma_h(acc[mt][nt], af[mt], bf[nt]);
        }
        __syncthreads();
    }

    // epilogue
    #pragma unroll
    for (int mt = 0; mt < 4; mt++) {
        #pragma unroll
        for (int nt = 0; nt < 4; nt++) {
            int col = n0 + wn0 + nt * 8 + tg * 2;
            float b0v = Bi[col], b1v = Bi[col + 1];
            #pragma unroll
            for (int h2 = 0; h2 < 2; h2++) {
                int row = m0 + wm0 + mt * 16 + g + h2 * 8;
                float v0 = (acc[mt][nt][h2*2 + 0] + b0v) * osc;
                float v1 = (acc[mt][nt][h2*2 + 1] + b1v) * osc;
                if (mode == 0) {
                    int b = row >> 11, s = row & 2047;
                    int hh = col >> 6, dh = col & 63;
                    size_t idx = (((size_t)(b * HEADS + hh)) * SEQ + s) * HDIM + dh;
                    *(__half2*)(Ho + idx) = __floats2half2_rn(v0, v1);
                } else {
                    *(float2*)(Cf + (size_t)row * DIM + col) = make_float2(v0, v1);
                }
            }
        }
    }
}

// ---------------------------------------------------------------------------
// fp16 attention: causal tile skipping + ex2.f16x2 softmax + mma rowsums +
// LPT-balanced static schedule. 296 CTAs, each handles 1-2 (bh,iq) items:
//   rank r (weight-sorted desc): bh = r&31, iq = 15-(r>>5), weight 2iq+2.
//   CTA j<80: single item rank j. CTA j in [80,296): pair (j, 591-j).
// smem halves: Q[128][72] | K[2][64][72] | V[2][64][72] | suf (64 floats)
// ---------------------------------------------------------------------------
#define AST     72
#define AQ_OFF  0
#define AK_OFF  (128*AST)
#define AV_OFF  (AK_OFF + 2*64*AST)
#define AH_TOT  (AV_OFF + 2*64*AST)
#define ASMEM   (AH_TOT*2 + 64*4)
#define NCTA_A  296

__global__ __launch_bounds__(256, 2) void attn_h(
    const __half* __restrict__ q, const __half* __restrict__ k,
    const __half* __restrict__ v, const float* __restrict__ Tsum,
    __half* __restrict__ ao)
{
    extern __shared__ __half sma[];
    float* suf = (float*)(sma + AH_TOT);

    const int tid = threadIdx.x, lane = tid & 31, wid = tid >> 5;
    const int g = lane >> 2, tg = lane & 3;
    const int j = blockIdx.x;
    const int nitems = (j < 80) ? 1 : 2;

    const uint32_t sBase = smem_u32(sma);
    const int kvRow = tid >> 3, kvCc = (tid & 7) * 8;
    const int bRowL = (lane & 7) + ((lane & 16) ? 8 : 0);
    const int bColH = (lane & 8) ? 8 : 0;
    const int vRowL = (lane & 7) + ((lane & 8) ? 8 : 0);
    const int vColH = (lane & 16) ? 8 : 0;
    const uint32_t stB = (uint32_t)(64 * AST * 2);
    const uint32_t kB0 = sBase + (uint32_t)((AK_OFF + bRowL * AST + bColH) * 2);
    const uint32_t vB0 = sBase + (uint32_t)((AV_OFF + vRowL * AST + vColH) * 2);
    const uint32_t onesb[2] = {0x3C003C00u, 0x3C003C00u};

    for (int it = 0; it < nitems; it++) {
        const int r  = (it == 0) ? j : (591 - j);
        const int bh = r & 31;
        const int iq = 15 - (r >> 5);
        const int b  = bh >> 4, h = bh & 15;
        const int q0 = iq * 128;
        const int ktEnd = 2 * iq + 2;

        const __half* qp = q + (size_t)bh * SEQ * HDIM;
        const __half* kp = k + (size_t)bh * SEQ * HDIM;
        const __half* vp = v + (size_t)bh * SEQ * HDIM;

        if (it > 0) __syncthreads();   // protect smem reuse across items

        // prologue: Q tile + K/V stage 0
        {
            const int row = tid >> 1, cc = (tid & 1) * 32;
            #pragma unroll
            for (int i = 0; i < 4; i++)
                CP16(sBase + (uint32_t)(AQ_OFF + row * AST + cc + i * 8) * 2,
                     qp + (size_t)(q0 + row) * HDIM + cc + i * 8);
            uint32_t sk = sBase + (uint32_t)AK_OFF * 2;
            uint32_t sv = sBase + (uint32_t)AV_OFF * 2;
            #pragma unroll
            for (int i = 0; i < 2; i++) {
                int rowk = kvRow + i * 32;
                uint32_t so = (uint32_t)(rowk * AST + kvCc) * 2;
                CP16(sk + so, kp + (size_t)rowk * HDIM + kvCc);
                CP16(sv + so, vp + (size_t)rowk * HDIM + kvCc);
            }
            CP_COMMIT();
        }

        // V column suffix sum over masked tiles (overlaps cp.async)
        if (tid < 64) {
            float acc = 0.f;
            const float* tp = Tsum + ((size_t)bh * 32) * HDIM + tid;
            for (int kt = ktEnd; kt < 32; kt++) acc += tp[(size_t)kt * HDIM];
            suf[tid] = acc;
        }

        CP_WAIT(0);
        __syncthreads();

        // persistent Q fragments
        uint32_t qf[4][4];
        {
            const uint32_t qA = sBase +
                (uint32_t)((AQ_OFF + (wid * 16 + (lane & 15)) * AST + (lane >> 4) * 8) * 2);
            #pragma unroll
            for (int ks = 0; ks < 4; ks++)
                LDSM_X4(qf[ks][0], qf[ks][1], qf[ks][2], qf[ks][3], qA + (uint32_t)(ks * 32));
        }

        {
            const __half* Kg = kp + (size_t)64 * HDIM;
            const __half* Vg = vp + (size_t)64 * HDIM;
            uint32_t sk = sBase + (uint32_t)(AK_OFF + 64 * AST) * 2;
            uint32_t sv = sBase + (uint32_t)(AV_OFF + 64 * AST) * 2;
            #pragma unroll
            for (int i = 0; i < 2; i++) {
                int row = kvRow + i * 32;
                uint32_t so = (uint32_t)(row * AST + kvCc) * 2;
                CP16(sk + so, Kg + (size_t)row * HDIM + kvCc);
                CP16(sv + so, Vg + (size_t)row * HDIM + kvCc);
            }
            CP_COMMIT();
        }

        float o[8][4];
        float rsacc[4] = {0.f, 0.f, 0.f, 0.f};
        #pragma unroll
        for (int nt = 0; nt < 8; nt++)
            #pragma unroll
            for (int rr = 0; rr < 4; rr++) o[nt][rr] = 0.f;

        const int row0 = q0 + wid * 16 + g;

        for (int kt = 0; kt < ktEnd; kt++) {
            const int cur = kt & 1;
            const int k0t = kt * 64;
            if (kt > 0) {
                CP_WAIT(0);
                __syncthreads();
                if (kt + 1 < ktEnd) {
                    const int st = cur ^ 1, ktn = kt + 1;
                    const __half* Kg = kp + (size_t)(ktn * 64) * HDIM;
                    const __half* Vg = vp + (size_t)(ktn * 64) * HDIM;
                    uint32_t sk = sBase + (uint32_t)(AK_OFF + st * 64 * AST) * 2;
                    uint32_t sv = sBase + (uint32_t)(AV_OFF + st * 64 * AST) * 2;
                    #pragma unroll
                    for (int i = 0; i < 2; i++) {
                        int row = kvRow + i * 32;
                        uint32_t so = (uint32_t)(row * AST + kvCc) * 2;
                        CP16(sk + so, Kg + (size_t)row * HDIM + kvCc);
                        CP16(sv + so, Vg + (size_t)row * HDIM + kvCc);
                    }
                    CP_COMMIT();
                }
            }

            // S = Qs @ K^T (accumulator = base-2 exponent argument)
            float s[8][4];
            #pragma unroll
            for (int nt = 0; nt < 8; nt++)
                #pragma unroll
                for (int rr = 0; rr < 4; rr++) s[nt][rr] = 0.f;
            {
                const uint32_t kB = kB0 + cur * stB;
                #pragma unroll
                for (int ks = 0; ks < 4; ks++) {
                    uint32_t bf[8][2];
                    #pragma unroll
                    for (int np = 0; np < 4; np++)
                        LDSM_X4(bf[np*2][0], bf[np*2][1], bf[np*2+1][0], bf[np*2+1][1],
                                kB + (uint32_t)((np * 16 * AST + ks * 16) * 2));
                    #pragma unroll
                    for (int nt = 0; nt < 8; nt++)
                        mma_h(s[nt], qf[ks], bf[nt]);
                }
            }

            // softmax: pack -> ex2.approx.f16x2 -> PV A-fragments.
            // mask (x=0 -> P=1.0) only on diagonal-touching tiles.
            const bool diag = (kt + 2 >= ktEnd);
            uint32_t pf[4][4];
            #pragma unroll
            for (int nt = 0; nt < 8; nt++) {
                float x0 = s[nt][0], x1 = s[nt][1], x2 = s[nt][2], x3 = s[nt][3];
                if (diag) {
                    int colj = k0t + nt * 8 + tg * 2;
                    x0 = (colj     > row0    ) ? 0.f : x0;
                    x1 = (colj + 1 > row0    ) ? 0.f : x1;
                    x2 = (colj     > row0 + 8) ? 0.f : x2;
                    x3 = (colj + 1 > row0 + 8) ? 0.f : x3;
                }
                uint32_t h01 = packh2(x0, x1), h23 = packh2(x2, x3);
                uint32_t p01, p23;
                asm("ex2.approx.f16x2 %0, %1;" : "=r"(p01) : "r"(h01));
                asm("ex2.approx.f16x2 %0, %1;" : "=r"(p23) : "r"(h23));
                pf[nt >> 1][(nt & 1) * 2 + 0] = p01;
                pf[nt >> 1][(nt & 1) * 2 + 1] = p23;
            }

            // O += P @ V, row sums += P @ ones
            {
                const uint32_t vB = vB0 + cur * stB;
                #pragma unroll
                for (int kp2 = 0; kp2 < 4; kp2++) {
                    uint32_t vf[8][2];
                    #pragma unroll
                    for (int np = 0; np < 4; np++)
                        LDSM_X4_T(vf[np*2][0], vf[np*2][1], vf[np*2+1][0], vf[np*2+1][1],
                                  vB + (uint32_t)((kp2 * 16 * AST + np * 16) * 2));
                    #pragma unroll
                    for (int nt = 0; nt < 8; nt++)
                        mma_h(o[nt], pf[kp2], vf[nt]);
                    mma_h(rsacc, pf[kp2], onesb);
                }
            }
        }

        // masked-tile contribution (P==1): suffix column sums of V
        #pragma unroll
        for (int nt = 0; nt < 8; nt++) {
            #pragma unroll
            for (int c2 = 0; c2 < 2; c2++) {
                float sv = suf[nt * 8 + tg * 2 + c2];
                o[nt][c2]     += sv;
                o[nt][2 + c2] += sv;
            }
        }

        const float nmask = (float)(SEQ - ktEnd * 64);
        const float inv0 = 1.0f / (rsacc[0] + nmask), inv1 = 1.0f / (rsacc[2] + nmask);

        // normalize + scatter fp16 into scrambled layout:
        // [b,h,s,dh] -> ao[b][2c + (s>>10)][s & 1023], c = h*64+dh
        const int s0 = row0, s1 = row0 + 8;
        #pragma unroll
        for (int nt = 0; nt < 8; nt++) {
            #pragma unroll
            for (int c2 = 0; c2 < 2; c2++) {
                int dh = nt * 8 + tg * 2 + c2;
                int c  = h * 64 + dh;
                size_t rowb = (size_t)b * SEQ * DIM;
                ao[rowb + (size_t)(2*c + (s0 >> 10)) * DIM + (s0 & 1023)] =
                    __float2half(o[nt][c2] * inv0);
                ao[rowb + (size_t)(2*c + (s1 >> 10)) * DIM + (s1 & 1023)] =
                    __float2half(o[nt][2 + c2] * inv1);
            }
        }
    }
}

// ---------------------------------------------------------------------------
extern "C" void kernel_launch(void* const* d_in, const int* in_sizes, int n_in,
                              void* d_out, int out_size)
{
    const float* x  = (const float*)d_in[0];
    const float* Wq = (const float*)d_in[2];
    const float* bq = (const float*)d_in[3];
    const float* Wk = (const float*)d_in[4];
    const float* bk = (const float*)d_in[5];
    const float* Wv = (const float*)d_in[6];
    const float* bv = (const float*)d_in[7];
    const float* Wo = (const float*)d_in[8];
    const float* bo = (const float*)d_in[9];
    float* out = (float*)d_out;

    __half *xh, *wh, *q, *k, *v, *aoh;
    float *ts;
    cudaGetSymbolAddress((void**)&xh,  g_xh);
    cudaGetSymbolAddress((void**)&wh,  g_wh);
    cudaGetSymbolAddress((void**)&q,   g_q);
    cudaGetSymbolAddress((void**)&k,   g_k);
    cudaGetSymbolAddress((void**)&v,   g_v);
    cudaGetSymbolAddress((void**)&aoh, g_aoh);
    cudaGetSymbolAddress((void**)&ts,  g_tsum);

    cudaFuncSetAttribute(gemm_h, cudaFuncAttributeMaxDynamicSharedMemorySize, GSMEM);
    cudaFuncSetAttribute(attn_h, cudaFuncAttributeMaxDynamicSharedMemorySize, ASMEM);

    convert_h<<<4096, 256>>>(x, Wq, Wk, Wv, Wo, xh, wh);

    // fused QKV projections (tile 128x128, 2 CTAs/SM)
    dim3 gg(DIM / 128, MTOT / 128, 3);   // (8, 32, 3)
    gemm_h<<<gg, 256, GSMEM>>>(xh, wh, bq, bk, bv, q, k, v, nullptr, 0);

    dim3 gt(32, BATCH * HEADS);          // per-tile V column sums
    tilesum_k<<<gt, 64>>>(v, ts);

    attn_h<<<NCTA_A, 256, ASMEM>>>(q, k, v, ts, aoh);

    // output projection (f32 out)
    dim3 go(DIM / 128, MTOT / 128, 1);
    gemm_h<<<go, 256, GSMEM>>>(aoh, wh + 3 * (size_t)DIM * DIM,
                               bo, bo, bo, q, q, q, out, 1);
}